// round 9
// baseline (speedup 1.0000x reference)
#include <cuda_runtime.h>

#define BB 64
#define TT 512
#define II 512
#define HH 1024
#define NCTA_DIR 64   // CTAs per direction; 128 total <= 148 SMs -> all co-resident

// ---------------- scratch (device globals; no allocations allowed) ----------
__device__ float g_Xrz[2][TT][BB][2 * HH]; // x@W_xr|x@W_xz (+bias), combined cols
__device__ float g_Xh [2][TT][BB][HH];     // x@W_xh (+bias)
__device__ float g_h  [2][BB][HH];         // current hidden state per direction
__device__ float g_RH [2][BB][HH];         // R * h   (phase1 -> phase2)
__device__ float g_Z  [2][BB][HH];         // Z gate  (phase1 -> phase2)
__device__ unsigned g_bar_count[2];
__device__ unsigned g_bar_gen[2];

#define HBAR(id) asm volatile("bar.sync %0, 256;" :: "r"(id) : "memory")

// ------------- per-direction software grid barrier (generation-based) -------
__device__ __forceinline__ void dir_barrier(int dir) {
    __syncthreads();
    if (threadIdx.x == 0) {
        volatile unsigned* vgen = (volatile unsigned*)&g_bar_gen[dir];
        unsigned my = *vgen;
        __threadfence();
        unsigned a = atomicAdd(&g_bar_count[dir], 1u);
        if (a == NCTA_DIR - 1) {
            g_bar_count[dir] = 0;
            __threadfence();
            atomicAdd(&g_bar_gen[dir], 1u);
        } else {
            while (*vgen == my) { }
            __threadfence();
        }
    }
    __syncthreads();
}

// ---------------- input projection: 6x GEMM (32768x512)@(512x1024)+bias -----
// CTA: 256 threads -> 128x64 tile, 32 outputs/thread (8 rows x 4 cols)
__global__ void __launch_bounds__(256) inproj_kernel(
    const float* __restrict__ x,
    const float* __restrict__ Wr_f, const float* __restrict__ br_f,
    const float* __restrict__ Wz_f, const float* __restrict__ bz_f,
    const float* __restrict__ Wh_f, const float* __restrict__ bh_f,
    const float* __restrict__ Wr_b, const float* __restrict__ br_b,
    const float* __restrict__ Wz_b, const float* __restrict__ bz_b,
    const float* __restrict__ Wh_b, const float* __restrict__ bh_b)
{
    const int mat  = blockIdx.z;   // 0..5 : dir*3 + gate
    const int dir  = mat / 3;
    const int gate = mat % 3;      // 0=r, 1=z, 2=h
    const float* W; const float* bias;
    switch (mat) {
        case 0: W = Wr_f; bias = br_f; break;
        case 1: W = Wz_f; bias = bz_f; break;
        case 2: W = Wh_f; bias = bh_f; break;
        case 3: W = Wr_b; bias = br_b; break;
        case 4: W = Wz_b; bias = bz_b; break;
        default: W = Wh_b; bias = bh_b; break;
    }

    const int mTile = blockIdx.x;             // 256 row tiles of 128
    const int cTile = blockIdx.y;             // 16 col tiles of 64
    const int w     = threadIdx.x >> 5;       // warp 0..7
    const int lane  = threadIdx.x & 31;
    const int hf    = lane >> 4;              // half-warp
    const int rbase = w * 16 + hf * 8;        // 8 rows per thread
    const int jc    = cTile * 64 + (lane & 15) * 4;  // 4 cols per thread

    __shared__ float xs[128][64];
    float acc[8][4];
    #pragma unroll
    for (int r = 0; r < 8; ++r)
        #pragma unroll
        for (int c = 0; c < 4; ++c) acc[r][c] = 0.f;

    const float* xbase = x + (size_t)(mTile * 128) * II;

    #pragma unroll 1
    for (int kb = 0; kb < II; kb += 64) {
        // stage 128x64 x-tile
        #pragma unroll
        for (int u = 0; u < 8; ++u) {
            int e  = threadIdx.x + 256 * u;     // 0..2047
            int r  = e >> 4;
            int c4 = (e & 15) * 4;
            *(float4*)&xs[r][c4] = *(const float4*)(xbase + r * II + kb + c4);
        }
        __syncthreads();
        #pragma unroll
        for (int k4 = 0; k4 < 16; ++k4) {
            const int k = kb + 4 * k4;
            const float4 w0 = *(const float4*)&W[(k + 0) * HH + jc];
            const float4 w1 = *(const float4*)&W[(k + 1) * HH + jc];
            const float4 w2 = *(const float4*)&W[(k + 2) * HH + jc];
            const float4 w3 = *(const float4*)&W[(k + 3) * HH + jc];
            #pragma unroll
            for (int r = 0; r < 8; ++r) {
                float4 xv = *(const float4*)&xs[rbase + r][4 * k4];
                acc[r][0] = fmaf(xv.x, w0.x, acc[r][0]);
                acc[r][1] = fmaf(xv.x, w0.y, acc[r][1]);
                acc[r][2] = fmaf(xv.x, w0.z, acc[r][2]);
                acc[r][3] = fmaf(xv.x, w0.w, acc[r][3]);
                acc[r][0] = fmaf(xv.y, w1.x, acc[r][0]);
                acc[r][1] = fmaf(xv.y, w1.y, acc[r][1]);
                acc[r][2] = fmaf(xv.y, w1.z, acc[r][2]);
                acc[r][3] = fmaf(xv.y, w1.w, acc[r][3]);
                acc[r][0] = fmaf(xv.z, w2.x, acc[r][0]);
                acc[r][1] = fmaf(xv.z, w2.y, acc[r][1]);
                acc[r][2] = fmaf(xv.z, w2.z, acc[r][2]);
                acc[r][3] = fmaf(xv.z, w2.w, acc[r][3]);
                acc[r][0] = fmaf(xv.w, w3.x, acc[r][0]);
                acc[r][1] = fmaf(xv.w, w3.y, acc[r][1]);
                acc[r][2] = fmaf(xv.w, w3.z, acc[r][2]);
                acc[r][3] = fmaf(xv.w, w3.w, acc[r][3]);
            }
        }
        __syncthreads();
    }

    const float4 bv = *(const float4*)&bias[jc];
    #pragma unroll
    for (int r = 0; r < 8; ++r) {
        int row = mTile * 128 + rbase + r;   // row = b*T + t
        int b   = row >> 9;                  // /512
        int t   = row & (TT - 1);
        float4 v;
        v.x = acc[r][0] + bv.x;
        v.y = acc[r][1] + bv.y;
        v.z = acc[r][2] + bv.z;
        v.w = acc[r][3] + bv.w;
        if (gate == 0)      *(float4*)&g_Xrz[dir][t][b][jc]      = v;
        else if (gate == 1) *(float4*)&g_Xrz[dir][t][b][HH + jc] = v;
        else                *(float4*)&g_Xh [dir][t][b][jc]      = v;
    }
}

// ---------------- persistent bidirectional GRU recurrence -------------------
// 128 CTAs x 512 threads, 1 CTA/SM. K-SPLIT: threads [0,256) compute k in
// [0,512), threads [256,512) compute k in [512,1024) with the IDENTICAL
// per-thread microkernel. Each half stages its own 64x64 tile in its own
// buffer and syncs with half-CTA named barriers, so 4 warps/SMSP interleave.
// Upper half deposits partial sums in its (then idle) tile buffer; lower
// half adds them and runs the epilogue.
// Dynamic smem (floats):
//   Wrz4 [32768]    : phase1 weights [(k>>2)*128 + col*4 + (k&3)]
//   Wh24 [16384]    : phase2 weights [(k>>2)*64  + col*4 + (k&3)]
//   ts [2][64][64]  : per-half staging tile (ts[1] doubles as psum buffer)
#define SM_WH2 32768
#define SM_TS  49152
#define SM_FLOATS (49152 + 2 * 64 * 64)

__global__ void __launch_bounds__(512) gru_rec_kernel(
    const float* __restrict__ hf0, const float* __restrict__ hb0,
    const float* __restrict__ Whr_f, const float* __restrict__ Whz_f, const float* __restrict__ Whh_f,
    const float* __restrict__ Whr_b, const float* __restrict__ Whz_b, const float* __restrict__ Whh_b,
    float* __restrict__ out)
{
    extern __shared__ float sm[];
    float* Wrz4 = sm;
    float* Wh24 = sm + SM_WH2;
    float (*ts)[64][64] = (float(*)[64][64])(sm + SM_TS);

    const int tid  = threadIdx.x;
    const int half = tid >> 8;          // 0: k in [0,512)   1: k in [512,1024)
    const int tidh = tid & 255;
    const int barid = 1 + half;
    const int koff  = half * 512;

    const int dir = blockIdx.x >> 6;
    const int c   = blockIdx.x & 63;

    const float* __restrict__ Whr = dir ? Whr_b : Whr_f;
    const float* __restrict__ Whz = dir ? Whz_b : Whz_f;
    const float* __restrict__ Whh = dir ? Whh_b : Whh_f;
    const float* __restrict__ h0  = dir ? hb0   : hf0;

    float* __restrict__ hstate = &g_h [dir][0][0];
    float* __restrict__ RH     = &g_RH[dir][0][0];
    float* __restrict__ Zb     = &g_Z [dir][0][0];
    float* __restrict__ psum   = &ts[1][0][0];   // upper tile doubles as psum

    // phase1 geometry (per half): 32 combined cols/CTA; 8 rows/thread
    const int lane1 = tidh & 31;
    const int rg1   = (tidh >> 5) * 8;
    const int jj    = c * 32 + lane1;            // 0..2047 combined [R|Z]
    const float* __restrict__ Wg = (jj < HH) ? Whr : Whz;
    const int jw    = jj & (HH - 1);

    // phase2 geometry (per half): 16 cols/CTA; 4 rows/thread
    const int lane2 = tidh & 15;
    const int rg2   = (tidh >> 4) * 4;
    const int j2    = c * 16 + lane2;

    // staging geometry: four float4 per thread per block (full 64x64 tile)
    int srow[4], scol[4];
    #pragma unroll
    for (int u = 0; u < 4; ++u) {
        int e = tidh + 256 * u;
        srow[u] = e >> 4;
        scol[u] = (e & 15) * 4;
    }

    // ---- one-time: cache this CTA's weight columns into SMEM (512 thr) ----
    {
        const int l1 = tid & 31;
        const int jwl = (c * 32 + l1) & (HH - 1);
        const float* __restrict__ Wgl = ((c * 32 + l1) < HH) ? Whr : Whz;
        for (int k = tid >> 5; k < HH; k += 16)
            Wrz4[(k >> 2) * 128 + l1 * 4 + (k & 3)] = Wgl[k * HH + jwl];
        const int l2 = tid & 15;
        const int j2l = c * 16 + l2;
        for (int k = tid >> 4; k < HH; k += 32)
            Wh24[(k >> 2) * 64 + l2 * 4 + (k & 3)] = Whh[k * HH + j2l];
    }
    // init hidden state (re-done every replay: deterministic)
    {
        int base = c * 1024;
        hstate[base + tid]       = h0[base + tid];
        hstate[base + 512 + tid] = h0[base + 512 + tid];
    }
    dir_barrier(dir);

    for (int step = 0; step < TT; ++step) {
        const int t = dir ? (TT - 1 - step) : step;

        // ------------------ phase 1: [R|Z] = sigmoid(h@W + x) -------------
        const float* __restrict__ xrz = &g_Xrz[dir][t][0][0];

        float xpre[8], hold1[8];
        if (half == 0) {
            #pragma unroll
            for (int r = 0; r < 8; ++r) {          // epilogue operand prefetch
                xpre[r]  = __ldg(&xrz[(rg1 + r) * (2 * HH) + jj]);
                hold1[r] = hstate[(rg1 + r) * HH + jw];
            }
        }

        // stage block 0 of this half
        #pragma unroll
        for (int u = 0; u < 4; ++u)
            *(float4*)&ts[half][srow[u]][scol[u]] =
                *(const float4*)&hstate[srow[u] * HH + koff + scol[u]];
        HBAR(barid);

        float acc[8] = {0.f,0.f,0.f,0.f,0.f,0.f,0.f,0.f};
        #pragma unroll 1
        for (int i = 0; i < 8; ++i) {
            float4 pf[4];
            if (i < 7) {
                const int kn = koff + (i + 1) * 64;
                #pragma unroll
                for (int u = 0; u < 4; ++u)
                    pf[u] = *(const float4*)&hstate[srow[u] * HH + kn + scol[u]];
            }
            #pragma unroll
            for (int k4 = 0; k4 < 16; ++k4) {
                const int q = half * 128 + i * 16 + k4;
                float4 wv = *(const float4*)&Wrz4[q * 128 + lane1 * 4];
                #pragma unroll
                for (int r = 0; r < 8; ++r) {
                    float4 hv = *(const float4*)&ts[half][rg1 + r][4 * k4];
                    acc[r] = fmaf(hv.x, wv.x, acc[r]);
                    acc[r] = fmaf(hv.y, wv.y, acc[r]);
                    acc[r] = fmaf(hv.z, wv.z, acc[r]);
                    acc[r] = fmaf(hv.w, wv.w, acc[r]);
                }
            }
            HBAR(barid);
            if (i < 7) {
                #pragma unroll
                for (int u = 0; u < 4; ++u)
                    *(float4*)&ts[half][srow[u]][scol[u]] = pf[u];
                HBAR(barid);
            }
        }
        // upper half deposits partials into its (now idle) tile buffer
        if (half == 1) {
            #pragma unroll
            for (int r = 0; r < 8; ++r)
                psum[(rg1 + r) * 32 + lane1] = acc[r];
        }
        __syncthreads();
        if (half == 0) {
            #pragma unroll
            for (int r = 0; r < 8; ++r) {
                const int b = rg1 + r;
                float pre = acc[r] + psum[b * 32 + lane1] + xpre[r];
                float s   = 1.f / (1.f + __expf(-pre));
                if (jj < HH) RH[b * HH + jw] = s * hold1[r];
                else         Zb[b * HH + jw] = s;
            }
        }
        dir_barrier(dir);

        // ------------------ phase 2: h = Z*tanh(RH@Whh + xh) + (1-Z)*h ----
        const float* __restrict__ xh = &g_Xh[dir][t][0][0];

        float xp2[4], zv[4], hv2[4];
        if (half == 0) {
            #pragma unroll
            for (int r = 0; r < 4; ++r) {
                const int b = rg2 + r;
                xp2[r] = __ldg(&xh[b * HH + j2]);
                zv[r]  = Zb[b * HH + j2];
                hv2[r] = hstate[b * HH + j2];
            }
        }

        #pragma unroll
        for (int u = 0; u < 4; ++u)
            *(float4*)&ts[half][srow[u]][scol[u]] =
                *(const float4*)&RH[srow[u] * HH + koff + scol[u]];
        HBAR(barid);

        float a2[4] = {0.f,0.f,0.f,0.f};
        #pragma unroll 1
        for (int i = 0; i < 8; ++i) {
            float4 pf[4];
            if (i < 7) {
                const int kn = koff + (i + 1) * 64;
                #pragma unroll
                for (int u = 0; u < 4; ++u)
                    pf[u] = *(const float4*)&RH[srow[u] * HH + kn + scol[u]];
            }
            #pragma unroll
            for (int k4 = 0; k4 < 16; ++k4) {
                const int q = half * 128 + i * 16 + k4;
                float4 wv = *(const float4*)&Wh24[q * 64 + lane2 * 4];
                #pragma unroll
                for (int r = 0; r < 4; ++r) {
                    float4 hv = *(const float4*)&ts[half][rg2 + r][4 * k4];
                    a2[r] = fmaf(hv.x, wv.x, a2[r]);
                    a2[r] = fmaf(hv.y, wv.y, a2[r]);
                    a2[r] = fmaf(hv.z, wv.z, a2[r]);
                    a2[r] = fmaf(hv.w, wv.w, a2[r]);
                }
            }
            HBAR(barid);
            if (i < 7) {
                #pragma unroll
                for (int u = 0; u < 4; ++u)
                    *(float4*)&ts[half][srow[u]][scol[u]] = pf[u];
                HBAR(barid);
            }
        }
        if (half == 1) {
            #pragma unroll
            for (int r = 0; r < 4; ++r)
                psum[(rg2 + r) * 16 + lane2] = a2[r];
        }
        __syncthreads();
        if (half == 0) {
            #pragma unroll
            for (int r = 0; r < 4; ++r) {
                const int b = rg2 + r;
                float htil = tanhf(a2[r] + psum[b * 16 + lane2] + xp2[r]);
                float hnew = zv[r] * htil + (1.f - zv[r]) * hv2[r];
                hstate[b * HH + j2] = hnew;
                out[(size_t)(b * TT + t) * (2 * HH) + dir * HH + j2] = hnew;
            }
        }
        dir_barrier(dir);
    }
}

// ---------------------------------------------------------------------------
extern "C" void kernel_launch(void* const* d_in, const int* in_sizes, int n_in,
                              void* d_out, int out_size) {
    (void)in_sizes; (void)n_in; (void)out_size;
    const float* x     = (const float*)d_in[0];
    const float* hf0   = (const float*)d_in[1];
    const float* hb0   = (const float*)d_in[2];
    const float* Whr_f = (const float*)d_in[3];
    const float* Wxr_f = (const float*)d_in[4];
    const float* br_f  = (const float*)d_in[5];
    const float* Whz_f = (const float*)d_in[6];
    const float* Wxz_f = (const float*)d_in[7];
    const float* bz_f  = (const float*)d_in[8];
    const float* Whh_f = (const float*)d_in[9];
    const float* Wxh_f = (const float*)d_in[10];
    const float* bh_f  = (const float*)d_in[11];
    const float* Whr_b = (const float*)d_in[12];
    const float* Wxr_b = (const float*)d_in[13];
    const float* br_b  = (const float*)d_in[14];
    const float* Whz_b = (const float*)d_in[15];
    const float* Wxz_b = (const float*)d_in[16];
    const float* bz_b  = (const float*)d_in[17];
    const float* Whh_b = (const float*)d_in[18];
    const float* Wxh_b = (const float*)d_in[19];
    const float* bh_b  = (const float*)d_in[20];
    float* out = (float*)d_out;

    static int smem_set = 0;
    if (!smem_set) {
        cudaFuncSetAttribute(gru_rec_kernel,
                             cudaFuncAttributeMaxDynamicSharedMemorySize,
                             SM_FLOATS * sizeof(float));
        smem_set = 1;
    }

    dim3 g1(TT * BB / 128, HH / 64, 6);
    inproj_kernel<<<g1, 256>>>(x,
        Wxr_f, br_f, Wxz_f, bz_f, Wxh_f, bh_f,
        Wxr_b, br_b, Wxz_b, bz_b, Wxh_b, bh_b);

    gru_rec_kernel<<<2 * NCTA_DIR, 512, SM_FLOATS * sizeof(float)>>>(hf0, hb0,
        Whr_f, Whz_f, Whh_f, Whr_b, Whz_b, Whh_b, out);
}

// round 10
// speedup vs baseline: 2.2610x; 2.2610x over previous
#include <cuda_runtime.h>
#include <cuda_bf16.h>
#include <cstdint>

#define BB 64
#define TT 512
#define II 512
#define HH 1024
#define NCTA_DIR 64

// ---------------- scratch (device globals) ----------------------------------
__device__ float g_Xrz[2][TT][BB][2 * HH];
__device__ float g_Xh [2][TT][BB][HH];
__device__ float g_h  [2][BB][HH];             // master hidden state (fp32)
__device__ float g_Z  [2][BB][HH];
__device__ __nv_bfloat16 g_h0s[2][BB][HH];     // bf16 splits of h
__device__ __nv_bfloat16 g_h1s[2][BB][HH];
__device__ __nv_bfloat16 g_R0s[2][BB][HH];     // bf16 splits of R*h
__device__ __nv_bfloat16 g_R1s[2][BB][HH];
__device__ unsigned g_bar_count[2];
__device__ unsigned g_bar_gen[2];

// ---------------- helpers ----------------------------------------------------
__device__ __forceinline__ uint32_t smem_u32(const void* p) {
    uint32_t a;
    asm("{ .reg .u64 t; cvta.to.shared.u64 t, %1; cvt.u32.u64 %0, t; }"
        : "=r"(a) : "l"(p));
    return a;
}
__device__ __forceinline__ void ldmA(uint32_t* a, uint32_t addr) {
    asm volatile("ldmatrix.sync.aligned.m8n8.x4.shared.b16 {%0,%1,%2,%3}, [%4];"
                 : "=r"(a[0]), "=r"(a[1]), "=r"(a[2]), "=r"(a[3]) : "r"(addr));
}
__device__ __forceinline__ void mmabf(float* d, const uint32_t* a,
                                      uint32_t b0, uint32_t b1) {
    asm volatile("mma.sync.aligned.m16n8k16.row.col.f32.bf16.bf16.f32 "
                 "{%0,%1,%2,%3},{%4,%5,%6,%7},{%8,%9},{%0,%1,%2,%3};"
                 : "+f"(d[0]), "+f"(d[1]), "+f"(d[2]), "+f"(d[3])
                 : "r"(a[0]), "r"(a[1]), "r"(a[2]), "r"(a[3]), "r"(b0), "r"(b1));
}
__device__ __forceinline__ uint32_t pk(float a, float b) {   // bf16(a)|bf16(b)<<16
    __nv_bfloat16 l = __float2bfloat16(a), h = __float2bfloat16(b);
    unsigned short ls = *(unsigned short*)&l, hs = *(unsigned short*)&h;
    return (uint32_t)ls | ((uint32_t)hs << 16);
}
__device__ __forceinline__ float bhi(float x) {              // float(bf16(x))
    return __bfloat162float(__float2bfloat16(x));
}

// ------------- per-direction software grid barrier ---------------------------
__device__ __forceinline__ void dir_barrier(int dir) {
    __syncthreads();
    if (threadIdx.x == 0) {
        volatile unsigned* vgen = (volatile unsigned*)&g_bar_gen[dir];
        unsigned my = *vgen;
        __threadfence();
        unsigned a = atomicAdd(&g_bar_count[dir], 1u);
        if (a == NCTA_DIR - 1) {
            g_bar_count[dir] = 0;
            __threadfence();
            atomicAdd(&g_bar_gen[dir], 1u);
        } else {
            while (*vgen == my) { }
            __threadfence();
        }
    }
    __syncthreads();
}

// ---------------- input projection (unchanged FFMA kernel) -------------------
__global__ void __launch_bounds__(256) inproj_kernel(
    const float* __restrict__ x,
    const float* __restrict__ Wr_f, const float* __restrict__ br_f,
    const float* __restrict__ Wz_f, const float* __restrict__ bz_f,
    const float* __restrict__ Wh_f, const float* __restrict__ bh_f,
    const float* __restrict__ Wr_b, const float* __restrict__ br_b,
    const float* __restrict__ Wz_b, const float* __restrict__ bz_b,
    const float* __restrict__ Wh_b, const float* __restrict__ bh_b)
{
    const int mat = blockIdx.z, dir = mat / 3, gate = mat % 3;
    const float* W; const float* bias;
    switch (mat) {
        case 0: W = Wr_f; bias = br_f; break;
        case 1: W = Wz_f; bias = bz_f; break;
        case 2: W = Wh_f; bias = bh_f; break;
        case 3: W = Wr_b; bias = br_b; break;
        case 4: W = Wz_b; bias = bz_b; break;
        default: W = Wh_b; bias = bh_b; break;
    }
    const int mTile = blockIdx.x, cTile = blockIdx.y;
    const int w = threadIdx.x >> 5, lane = threadIdx.x & 31;
    const int rbase = w * 16 + (lane >> 4) * 8;
    const int jc = cTile * 64 + (lane & 15) * 4;

    __shared__ float xs[128][64];
    float acc[8][4];
    #pragma unroll
    for (int r = 0; r < 8; ++r)
        #pragma unroll
        for (int cc = 0; cc < 4; ++cc) acc[r][cc] = 0.f;

    const float* xbase = x + (size_t)(mTile * 128) * II;
    #pragma unroll 1
    for (int kb = 0; kb < II; kb += 64) {
        #pragma unroll
        for (int u = 0; u < 8; ++u) {
            int e = threadIdx.x + 256 * u;
            *(float4*)&xs[e >> 4][(e & 15) * 4] =
                *(const float4*)(xbase + (e >> 4) * II + kb + (e & 15) * 4);
        }
        __syncthreads();
        #pragma unroll
        for (int k4 = 0; k4 < 16; ++k4) {
            const int k = kb + 4 * k4;
            const float4 w0 = *(const float4*)&W[(k + 0) * HH + jc];
            const float4 w1 = *(const float4*)&W[(k + 1) * HH + jc];
            const float4 w2 = *(const float4*)&W[(k + 2) * HH + jc];
            const float4 w3 = *(const float4*)&W[(k + 3) * HH + jc];
            #pragma unroll
            for (int r = 0; r < 8; ++r) {
                float4 xv = *(const float4*)&xs[rbase + r][4 * k4];
                acc[r][0] = fmaf(xv.x, w0.x, acc[r][0]);
                acc[r][1] = fmaf(xv.x, w0.y, acc[r][1]);
                acc[r][2] = fmaf(xv.x, w0.z, acc[r][2]);
                acc[r][3] = fmaf(xv.x, w0.w, acc[r][3]);
                acc[r][0] = fmaf(xv.y, w1.x, acc[r][0]);
                acc[r][1] = fmaf(xv.y, w1.y, acc[r][1]);
                acc[r][2] = fmaf(xv.y, w1.z, acc[r][2]);
                acc[r][3] = fmaf(xv.y, w1.w, acc[r][3]);
                acc[r][0] = fmaf(xv.z, w2.x, acc[r][0]);
                acc[r][1] = fmaf(xv.z, w2.y, acc[r][1]);
                acc[r][2] = fmaf(xv.z, w2.z, acc[r][2]);
                acc[r][3] = fmaf(xv.z, w2.w, acc[r][3]);
                acc[r][0] = fmaf(xv.w, w3.x, acc[r][0]);
                acc[r][1] = fmaf(xv.w, w3.y, acc[r][1]);
                acc[r][2] = fmaf(xv.w, w3.z, acc[r][2]);
                acc[r][3] = fmaf(xv.w, w3.w, acc[r][3]);
            }
        }
        __syncthreads();
    }
    const float4 bv = *(const float4*)&bias[jc];
    #pragma unroll
    for (int r = 0; r < 8; ++r) {
        int row = mTile * 128 + rbase + r;
        int b = row >> 9, t = row & (TT - 1);
        float4 v;
        v.x = acc[r][0] + bv.x; v.y = acc[r][1] + bv.y;
        v.z = acc[r][2] + bv.z; v.w = acc[r][3] + bv.w;
        if (gate == 0)      *(float4*)&g_Xrz[dir][t][b][jc]      = v;
        else if (gate == 1) *(float4*)&g_Xrz[dir][t][b][HH + jc] = v;
        else                *(float4*)&g_Xh [dir][t][b][jc]      = v;
    }
}

// ---------------- persistent tensor-core recurrence --------------------------
// SMEM bytes: Bf1 [4n][64q][32 lane][4 u32]  = 131072  (phase1 B-fragments)
//             Bf2 [2n][64q][32 lane][4 u32]  =  65536  (phase2 B-fragments)
//             At  [2 split][64][72 bf16]     =  18432  (A staging, pitch 72)
#define SM_BF1 0
#define SM_BF2 131072
#define SM_AT  196608
#define AT_STR 9216          // 64*144 bytes per split
#define SM_BYTES 215040

__global__ void __launch_bounds__(512) gru_rec_kernel(
    const float* __restrict__ hf0, const float* __restrict__ hb0,
    const float* __restrict__ Whr_f, const float* __restrict__ Whz_f, const float* __restrict__ Whh_f,
    const float* __restrict__ Whr_b, const float* __restrict__ Whz_b, const float* __restrict__ Whh_b,
    float* __restrict__ out)
{
    extern __shared__ char smc[];
    const uint32_t smb = smem_u32(smc);
    uint32_t* Bf1 = (uint32_t*)(smc + SM_BF1);
    uint32_t* Bf2 = (uint32_t*)(smc + SM_BF2);

    const int tid = threadIdx.x;
    const int w = tid >> 5, lane = tid & 31;
    const int gid = lane >> 2, tig = lane & 3;
    const int dir = blockIdx.x >> 6;
    const int c   = blockIdx.x & 63;
    const bool isR = (c < 32);

    const float* __restrict__ Whr = dir ? Whr_b : Whr_f;
    const float* __restrict__ Whz = dir ? Whz_b : Whz_f;
    const float* __restrict__ Whh = dir ? Whh_b : Whh_f;
    const float* __restrict__ h0in = dir ? hb0 : hf0;
    const float* __restrict__ Wg  = isR ? Whr : Whz;

    // ---- one-time: weight splits into B-fragment layout ----
    for (int e = tid; e < 8192; e += 512) {          // phase1: 4n x 64q x 32lane
        int le = e & 31, q = (e >> 5) & 63, n = e >> 11;
        int ge = le >> 2, te = le & 3;
        int jw = (c * 32 + n * 8 + ge) & (HH - 1);
        #pragma unroll
        for (int breg = 0; breg < 2; ++breg) {
            int k0 = q * 16 + breg * 8 + 2 * te;
            float f0 = Wg[k0 * HH + jw], f1 = Wg[(k0 + 1) * HH + jw];
            Bf1[e * 4 + breg]     = pk(bhi(f0), bhi(f1));
            Bf1[e * 4 + 2 + breg] = pk(f0 - bhi(f0), f1 - bhi(f1));
        }
    }
    for (int e = tid; e < 4096; e += 512) {          // phase2: 2n x 64q x 32lane
        int le = e & 31, q = (e >> 5) & 63, n = (e >> 11) & 1;
        int ge = le >> 2, te = le & 3;
        int j2w = c * 16 + n * 8 + ge;
        #pragma unroll
        for (int breg = 0; breg < 2; ++breg) {
            int k0 = q * 16 + breg * 8 + 2 * te;
            float f0 = Whh[k0 * HH + j2w], f1 = Whh[(k0 + 1) * HH + j2w];
            Bf2[e * 4 + breg]     = pk(bhi(f0), bhi(f1));
            Bf2[e * 4 + 2 + breg] = pk(f0 - bhi(f0), f1 - bhi(f1));
        }
    }
    // ---- init hidden state + splits (every replay: deterministic) ----
    {
        int base = c * 1024;
        #pragma unroll
        for (int u = 0; u < 2; ++u) {
            int idx = base + u * 512 + tid;
            float v = h0in[idx];
            (&g_h[dir][0][0])[idx] = v;
            float v0 = bhi(v);
            (&g_h0s[dir][0][0])[idx] = __float2bfloat16(v);
            (&g_h1s[dir][0][0])[idx] = __float2bfloat16(v - v0);
        }
    }
    dir_barrier(dir);

    // warp tiling
    const int m1 = w >> 2, n1 = w & 3;               // phase1: 4M x 4N, full K
    const int wk = w >> 3, w8 = w & 7;               // phase2: 4M x 2N x 2K
    const int m2 = w8 >> 1, n2 = w8 & 1;
    // staging: thread -> (row, 16B segment)
    const int grow = tid >> 3, gseg = tid & 7;
    const int goff = grow * HH + gseg * 8;           // bf16 elements
    const uint32_t smoff = grow * 144 + gseg * 16;   // bytes in At
    // ldmatrix A addresses (per phase, per split; +ks*32 per k-step)
    const uint32_t aoff1 = (m1 * 16 + (lane & 15)) * 144 + (lane >> 4) * 16;
    const uint32_t aoff2 = (m2 * 16 + (lane & 15)) * 144 + (lane >> 4) * 16;

    const __nv_bfloat16* __restrict__ h0p = &g_h0s[dir][0][0];
    const __nv_bfloat16* __restrict__ h1p = &g_h1s[dir][0][0];
    const __nv_bfloat16* __restrict__ R0p = &g_R0s[dir][0][0];
    const __nv_bfloat16* __restrict__ R1p = &g_R1s[dir][0][0];
    float* __restrict__ red = (float*)(smc + SM_AT);     // reuse At after GEMM

    for (int step = 0; step < TT; ++step) {
        const int t = dir ? (TT - 1 - step) : step;

        // ================= phase 1: [R|Z] = sigmoid(h@W + x) ==============
        float A0[4] = {0,0,0,0}, A1[4] = {0,0,0,0}, A2[4] = {0,0,0,0};
        uint4 v0 = *(const uint4*)(h0p + goff);
        uint4 v1 = *(const uint4*)(h1p + goff);
        #pragma unroll 1
        for (int kb = 0; kb < 16; ++kb) {
            __syncthreads();
            *(uint4*)(smc + SM_AT + smoff)          = v0;
            *(uint4*)(smc + SM_AT + AT_STR + smoff) = v1;
            __syncthreads();
            if (kb < 15) {
                v0 = *(const uint4*)(h0p + goff + (kb + 1) * 64);
                v1 = *(const uint4*)(h1p + goff + (kb + 1) * 64);
            }
            #pragma unroll
            for (int ks = 0; ks < 4; ++ks) {
                uint32_t a0[4], a1[4];
                ldmA(a0, smb + SM_AT + aoff1 + ks * 32);
                ldmA(a1, smb + SM_AT + AT_STR + aoff1 + ks * 32);
                uint4 bb = *(const uint4*)&Bf1[((n1 * 64 + kb * 4 + ks) * 32 + lane) * 4];
                mmabf(A0, a0, bb.x, bb.y);
                mmabf(A1, a1, bb.x, bb.y);
                mmabf(A2, a0, bb.z, bb.w);
            }
        }
        {   // epilogue: c0=(g,2t) c1=(g,2t+1) c2=(g+8,2t) c3=(g+8,2t+1)
            const float* __restrict__ xrz = &g_Xrz[dir][t][0][0];
            #pragma unroll
            for (int i = 0; i < 4; ++i) {
                int b  = m1 * 16 + gid + (i >> 1) * 8;
                int cc = n1 * 8 + 2 * tig + (i & 1);
                int jj = c * 32 + cc;
                float pre = A0[i] + A1[i] + A2[i] + xrz[b * (2 * HH) + jj];
                float s = 1.f / (1.f + __expf(-pre));
                if (isR) {
                    float v = s * g_h[dir][b][jj];
                    float vh = bhi(v);
                    g_R0s[dir][b][jj] = __float2bfloat16(v);
                    g_R1s[dir][b][jj] = __float2bfloat16(v - vh);
                } else {
                    g_Z[dir][b][jj - HH] = s;
                }
            }
        }
        dir_barrier(dir);

        // ======== phase 2: h = Z*tanh(RH@Whh + xh) + (1-Z)*h ==============
        float C0[4] = {0,0,0,0}, C1[4] = {0,0,0,0}, C2[4] = {0,0,0,0};
        v0 = *(const uint4*)(R0p + goff);
        v1 = *(const uint4*)(R1p + goff);
        #pragma unroll 1
        for (int kb = 0; kb < 16; ++kb) {
            __syncthreads();
            *(uint4*)(smc + SM_AT + smoff)          = v0;
            *(uint4*)(smc + SM_AT + AT_STR + smoff) = v1;
            __syncthreads();
            if (kb < 15) {
                v0 = *(const uint4*)(R0p + goff + (kb + 1) * 64);
                v1 = *(const uint4*)(R1p + goff + (kb + 1) * 64);
            }
            if ((kb >> 3) == wk) {
                #pragma unroll
                for (int ks = 0; ks < 4; ++ks) {
                    uint32_t a0[4], a1[4];
                    ldmA(a0, smb + SM_AT + aoff2 + ks * 32);
                    ldmA(a1, smb + SM_AT + AT_STR + aoff2 + ks * 32);
                    uint4 bb = *(const uint4*)&Bf2[((n2 * 64 + kb * 4 + ks) * 32 + lane) * 4];
                    mmabf(C0, a0, bb.x, bb.y);
                    mmabf(C1, a1, bb.x, bb.y);
                    mmabf(C2, a0, bb.z, bb.w);
                }
            }
        }
        __syncthreads();
        if (wk == 1) {
            #pragma unroll
            for (int i = 0; i < 4; ++i) {
                int r  = m2 * 16 + gid + (i >> 1) * 8;
                int cc = n2 * 8 + 2 * tig + (i & 1);
                red[r * 16 + cc] = C0[i] + C1[i] + C2[i];
            }
        }
        __syncthreads();
        if (wk == 0) {
            const float* __restrict__ xh = &g_Xh[dir][t][0][0];
            #pragma unroll
            for (int i = 0; i < 4; ++i) {
                int b  = m2 * 16 + gid + (i >> 1) * 8;
                int cc = n2 * 8 + 2 * tig + (i & 1);
                int j2 = c * 16 + cc;
                float sum = C0[i] + C1[i] + C2[i] + red[b * 16 + cc];
                float htil = tanhf(sum + xh[b * HH + j2]);
                float z    = g_Z[dir][b][j2];
                float hold = g_h[dir][b][j2];
                float hnew = z * htil + (1.f - z) * hold;
                g_h[dir][b][j2] = hnew;
                float nh = bhi(hnew);
                g_h0s[dir][b][j2] = __float2bfloat16(hnew);
                g_h1s[dir][b][j2] = __float2bfloat16(hnew - nh);
                out[(size_t)(b * TT + t) * (2 * HH) + dir * HH + j2] = hnew;
            }
        }
        dir_barrier(dir);
    }
}

// ---------------------------------------------------------------------------
extern "C" void kernel_launch(void* const* d_in, const int* in_sizes, int n_in,
                              void* d_out, int out_size) {
    (void)in_sizes; (void)n_in; (void)out_size;
    const float* x     = (const float*)d_in[0];
    const float* hf0   = (const float*)d_in[1];
    const float* hb0   = (const float*)d_in[2];
    const float* Whr_f = (const float*)d_in[3];
    const float* Wxr_f = (const float*)d_in[4];
    const float* br_f  = (const float*)d_in[5];
    const float* Whz_f = (const float*)d_in[6];
    const float* Wxz_f = (const float*)d_in[7];
    const float* bz_f  = (const float*)d_in[8];
    const float* Whh_f = (const float*)d_in[9];
    const float* Wxh_f = (const float*)d_in[10];
    const float* bh_f  = (const float*)d_in[11];
    const float* Whr_b = (const float*)d_in[12];
    const float* Wxr_b = (const float*)d_in[13];
    const float* br_b  = (const float*)d_in[14];
    const float* Whz_b = (const float*)d_in[15];
    const float* Wxz_b = (const float*)d_in[16];
    const float* bz_b  = (const float*)d_in[17];
    const float* Whh_b = (const float*)d_in[18];
    const float* Wxh_b = (const float*)d_in[19];
    const float* bh_b  = (const float*)d_in[20];
    float* out = (float*)d_out;

    static int smem_set = 0;
    if (!smem_set) {
        cudaFuncSetAttribute(gru_rec_kernel,
                             cudaFuncAttributeMaxDynamicSharedMemorySize,
                             SM_BYTES);
        smem_set = 1;
    }

    dim3 g1(TT * BB / 128, HH / 64, 6);
    inproj_kernel<<<g1, 256>>>(x,
        Wxr_f, br_f, Wxz_f, bz_f, Wxh_f, bh_f,
        Wxr_b, br_b, Wxz_b, bz_b, Wxh_b, bh_b);

    gru_rec_kernel<<<2 * NCTA_DIR, 512, SM_BYTES>>>(hf0, hb0,
        Whr_f, Whz_f, Whh_f, Whr_b, Whz_b, Whh_b, out);
}

// round 11
// speedup vs baseline: 2.4800x; 1.0969x over previous
#include <cuda_runtime.h>
#include <cuda_bf16.h>
#include <cstdint>

#define BB 64
#define TT 512
#define II 512
#define HH 1024
#define NCTA_DIR 64

// ---------------- scratch (device globals) ----------------------------------
__device__ float g_Xrz[2][TT][BB][2 * HH];
__device__ float g_Xh [2][TT][BB][HH];
__device__ float g_h  [2][BB][HH];             // master hidden state (fp32)
__device__ float g_Z  [2][BB][HH];
__device__ __nv_bfloat16 g_h0s[2][BB][HH];     // bf16 splits of h
__device__ __nv_bfloat16 g_h1s[2][BB][HH];
__device__ __nv_bfloat16 g_R0s[2][BB][HH];     // bf16 splits of R*h
__device__ __nv_bfloat16 g_R1s[2][BB][HH];
__device__ uint4 g_Wf[2][3][128][32][32];      // x-weight B-fragments (prep)
__device__ unsigned g_bar_count[2];
__device__ unsigned g_bar_gen[2];

// ---------------- helpers ----------------------------------------------------
__device__ __forceinline__ uint32_t smem_u32(const void* p) {
    uint32_t a;
    asm("{ .reg .u64 t; cvta.to.shared.u64 t, %1; cvt.u32.u64 %0, t; }"
        : "=r"(a) : "l"(p));
    return a;
}
__device__ __forceinline__ void ldmA(uint32_t* a, uint32_t addr) {
    asm volatile("ldmatrix.sync.aligned.m8n8.x4.shared.b16 {%0,%1,%2,%3}, [%4];"
                 : "=r"(a[0]), "=r"(a[1]), "=r"(a[2]), "=r"(a[3]) : "r"(addr));
}
__device__ __forceinline__ void mmabf(float* d, const uint32_t* a,
                                      uint32_t b0, uint32_t b1) {
    asm volatile("mma.sync.aligned.m16n8k16.row.col.f32.bf16.bf16.f32 "
                 "{%0,%1,%2,%3},{%4,%5,%6,%7},{%8,%9},{%0,%1,%2,%3};"
                 : "+f"(d[0]), "+f"(d[1]), "+f"(d[2]), "+f"(d[3])
                 : "r"(a[0]), "r"(a[1]), "r"(a[2]), "r"(a[3]), "r"(b0), "r"(b1));
}
__device__ __forceinline__ uint32_t pk(float a, float b) {
    __nv_bfloat16 l = __float2bfloat16(a), h = __float2bfloat16(b);
    unsigned short ls = *(unsigned short*)&l, hs = *(unsigned short*)&h;
    return (uint32_t)ls | ((uint32_t)hs << 16);
}
__device__ __forceinline__ float bhi(float x) {
    return __bfloat162float(__float2bfloat16(x));
}

// ------------- per-direction software grid barrier ---------------------------
__device__ __forceinline__ void dir_barrier(int dir) {
    __syncthreads();
    if (threadIdx.x == 0) {
        volatile unsigned* vgen = (volatile unsigned*)&g_bar_gen[dir];
        unsigned my = *vgen;
        __threadfence();
        unsigned a = atomicAdd(&g_bar_count[dir], 1u);
        if (a == NCTA_DIR - 1) {
            g_bar_count[dir] = 0;
            __threadfence();
            atomicAdd(&g_bar_gen[dir], 1u);
        } else {
            while (*vgen == my) { }
            __threadfence();
        }
    }
    __syncthreads();
}

// ---------------- weight-fragment prep for inproj ---------------------------
// g_Wf[dir][gate][n_tile][q][lane] = {b0_s0, b1_s0, b0_s1, b1_s1}
__global__ void __launch_bounds__(256) wprep_kernel(
    const float* __restrict__ Wr_f, const float* __restrict__ Wz_f, const float* __restrict__ Wh_f,
    const float* __restrict__ Wr_b, const float* __restrict__ Wz_b, const float* __restrict__ Wh_b)
{
    const int gate = blockIdx.y, dir = blockIdx.z;
    const float* W;
    if (dir == 0) W = (gate == 0) ? Wr_f : (gate == 1) ? Wz_f : Wh_f;
    else          W = (gate == 0) ? Wr_b : (gate == 1) ? Wz_b : Wh_b;

    int e = blockIdx.x * 256 + threadIdx.x;      // 0..131071
    int lane = e & 31, q = (e >> 5) & 31, nt = e >> 10;
    int ge = lane >> 2, te = lane & 3;
    int j = nt * 8 + ge;
    uint32_t fr[4];
    #pragma unroll
    for (int breg = 0; breg < 2; ++breg) {
        int k0 = q * 16 + breg * 8 + 2 * te;
        float f0 = W[k0 * HH + j], f1 = W[(k0 + 1) * HH + j];
        fr[breg]     = pk(bhi(f0), bhi(f1));
        fr[2 + breg] = pk(f0 - bhi(f0), f1 - bhi(f1));
    }
    g_Wf[dir][gate][nt][q][lane] = make_uint4(fr[0], fr[1], fr[2], fr[3]);
}

// ---------------- inproj on tensor cores -------------------------------------
// grid (256 mTiles, 32 cTiles, 2 dirs); 256 thr. CTA: 128 rows x 32 cols x 3 gates.
// Warps: 4M (2 m-tiles each) x 2N (2 n-tiles each).
__global__ void __launch_bounds__(256) inproj_mma_kernel(
    const float* __restrict__ x,
    const float* __restrict__ br_f, const float* __restrict__ bz_f, const float* __restrict__ bh_f,
    const float* __restrict__ br_b, const float* __restrict__ bz_b, const float* __restrict__ bh_b)
{
    __shared__ char xs0[128 * 144];
    __shared__ char xs1[128 * 144];
    const uint32_t s0 = smem_u32(xs0), s1 = smem_u32(xs1);

    const int mTile = blockIdx.x, cTile = blockIdx.y, dir = blockIdx.z;
    const int tid = threadIdx.x, w = tid >> 5, lane = tid & 31;
    const int gid = lane >> 2, tig = lane & 3;
    const int wm = w >> 1, wn = w & 1;

    const float* bias[3] = { dir ? br_b : br_f, dir ? bz_b : bz_f, dir ? bh_b : bh_f };

    float C[3][2][2][4];
    #pragma unroll
    for (int g = 0; g < 3; ++g)
        #pragma unroll
        for (int mt = 0; mt < 2; ++mt)
            #pragma unroll
            for (int nt = 0; nt < 2; ++nt)
                #pragma unroll
                for (int i = 0; i < 4; ++i) C[g][mt][nt][i] = 0.f;

    const int srow = tid >> 1, sq = (tid & 1) * 8;   // 8 float4 per thread: 2 rows? no:
    // staging map: e = tid + 256*u, u 0..7 -> row = e>>4 (0..127), q4 = e&15
    const float* xb = x + (size_t)(mTile * 128) * II;
    (void)srow; (void)sq;

    #pragma unroll 1
    for (int kb = 0; kb < 8; ++kb) {
        __syncthreads();
        #pragma unroll
        for (int u = 0; u < 8; ++u) {
            int e = tid + 256 * u;
            int row = e >> 4, q4 = e & 15;
            float4 v = *(const float4*)(xb + row * II + kb * 64 + q4 * 4);
            uint32_t h01 = pk(bhi(v.x), bhi(v.y));
            uint32_t h23 = pk(bhi(v.z), bhi(v.w));
            uint32_t r01 = pk(v.x - bhi(v.x), v.y - bhi(v.y));
            uint32_t r23 = pk(v.z - bhi(v.z), v.w - bhi(v.w));
            *(uint2*)(xs0 + row * 144 + q4 * 8) = make_uint2(h01, h23);
            *(uint2*)(xs1 + row * 144 + q4 * 8) = make_uint2(r01, r23);
        }
        __syncthreads();
        #pragma unroll
        for (int ks = 0; ks < 4; ++ks) {
            uint32_t a0[2][4], a1[2][4];
            #pragma unroll
            for (int mt = 0; mt < 2; ++mt) {
                uint32_t ao = (uint32_t)((wm * 32 + mt * 16 + (lane & 15)) * 144
                                         + (lane >> 4) * 16 + ks * 32);
                ldmA(a0[mt], s0 + ao);
                ldmA(a1[mt], s1 + ao);
            }
            #pragma unroll
            for (int g = 0; g < 3; ++g) {
                #pragma unroll
                for (int nt = 0; nt < 2; ++nt) {
                    uint4 bb = g_Wf[dir][g][cTile * 4 + wn * 2 + nt][kb * 4 + ks][lane];
                    #pragma unroll
                    for (int mt = 0; mt < 2; ++mt) {
                        mmabf(C[g][mt][nt], a0[mt], bb.x, bb.y);
                        mmabf(C[g][mt][nt], a1[mt], bb.x, bb.y);
                        mmabf(C[g][mt][nt], a0[mt], bb.z, bb.w);
                    }
                }
            }
        }
    }
    // epilogue
    #pragma unroll
    for (int g = 0; g < 3; ++g) {
        #pragma unroll
        for (int mt = 0; mt < 2; ++mt) {
            #pragma unroll
            for (int nt = 0; nt < 2; ++nt) {
                #pragma unroll
                for (int i = 0; i < 4; ++i) {
                    int row = mTile * 128 + wm * 32 + mt * 16 + gid + (i >> 1) * 8;
                    int j   = cTile * 32 + wn * 16 + nt * 8 + 2 * tig + (i & 1);
                    int b = row >> 9, t = row & (TT - 1);
                    float v = C[g][mt][nt][i] + bias[g][j];
                    if (g == 0)      g_Xrz[dir][t][b][j]      = v;
                    else if (g == 1) g_Xrz[dir][t][b][HH + j] = v;
                    else             g_Xh [dir][t][b][j]      = v;
                }
            }
        }
    }
}

// ---------------- persistent tensor-core recurrence --------------------------
// SMEM: Bf1 131072 | Bf2 65536 | At 2 x (64 x 272B) = 34816  -> 231424 B
#define SM_BF1 0
#define SM_BF2 131072
#define SM_AT  196608
#define AT_STR 17408
#define SM_BYTES 231424

__global__ void __launch_bounds__(512) gru_rec_kernel(
    const float* __restrict__ hf0, const float* __restrict__ hb0,
    const float* __restrict__ Whr_f, const float* __restrict__ Whz_f, const float* __restrict__ Whh_f,
    const float* __restrict__ Whr_b, const float* __restrict__ Whz_b, const float* __restrict__ Whh_b,
    float* __restrict__ out)
{
    extern __shared__ char smc[];
    const uint32_t smb = smem_u32(smc);
    uint32_t* Bf1 = (uint32_t*)(smc + SM_BF1);
    uint32_t* Bf2 = (uint32_t*)(smc + SM_BF2);

    const int tid = threadIdx.x;
    const int w = tid >> 5, lane = tid & 31;
    const int gid = lane >> 2, tig = lane & 3;
    const int dir = blockIdx.x >> 6;
    const int c   = blockIdx.x & 63;
    const bool isR = (c < 32);

    const float* __restrict__ Whr = dir ? Whr_b : Whr_f;
    const float* __restrict__ Whz = dir ? Whz_b : Whz_f;
    const float* __restrict__ Whh = dir ? Whh_b : Whh_f;
    const float* __restrict__ h0in = dir ? hb0 : hf0;
    const float* __restrict__ Wg  = isR ? Whr : Whz;

    // ---- one-time: weight splits into B-fragment layout ----
    for (int e = tid; e < 8192; e += 512) {
        int le = e & 31, q = (e >> 5) & 63, n = e >> 11;
        int ge = le >> 2, te = le & 3;
        int jw = (c * 32 + n * 8 + ge) & (HH - 1);
        #pragma unroll
        for (int breg = 0; breg < 2; ++breg) {
            int k0 = q * 16 + breg * 8 + 2 * te;
            float f0 = Wg[k0 * HH + jw], f1 = Wg[(k0 + 1) * HH + jw];
            Bf1[e * 4 + breg]     = pk(bhi(f0), bhi(f1));
            Bf1[e * 4 + 2 + breg] = pk(f0 - bhi(f0), f1 - bhi(f1));
        }
    }
    for (int e = tid; e < 4096; e += 512) {
        int le = e & 31, q = (e >> 5) & 63, n = (e >> 11) & 1;
        int ge = le >> 2, te = le & 3;
        int j2w = c * 16 + n * 8 + ge;
        #pragma unroll
        for (int breg = 0; breg < 2; ++breg) {
            int k0 = q * 16 + breg * 8 + 2 * te;
            float f0 = Whh[k0 * HH + j2w], f1 = Whh[(k0 + 1) * HH + j2w];
            Bf2[e * 4 + breg]     = pk(bhi(f0), bhi(f1));
            Bf2[e * 4 + 2 + breg] = pk(f0 - bhi(f0), f1 - bhi(f1));
        }
    }
    {
        int base = c * 1024;
        #pragma unroll
        for (int u = 0; u < 2; ++u) {
            int idx = base + u * 512 + tid;
            float v = h0in[idx];
            (&g_h[dir][0][0])[idx] = v;
            (&g_h0s[dir][0][0])[idx] = __float2bfloat16(v);
            (&g_h1s[dir][0][0])[idx] = __float2bfloat16(v - bhi(v));
        }
    }
    dir_barrier(dir);

    const int m1 = w >> 2, n1 = w & 3;          // phase1: 4M x 4N, full K
    const int wk = w >> 3, w8 = w & 7;          // phase2: 4M x 2N x 2K-split
    const int m2 = w8 >> 1, n2 = w8 & 1;

    // staging: 2 chunks per thread per split per 128-wide block
    int grow[2], gseg[2];
    #pragma unroll
    for (int u = 0; u < 2; ++u) {
        int e = tid + 512 * u;
        grow[u] = e >> 4;       // 0..63
        gseg[u] = e & 15;       // 16B segment (8 bf16)
    }
    const uint32_t aoff1 = (uint32_t)((m1 * 16 + (lane & 15)) * 272 + (lane >> 4) * 16);
    const uint32_t aoff2 = (uint32_t)((m2 * 16 + (lane & 15)) * 272 + (lane >> 4) * 16);

    const __nv_bfloat16* __restrict__ h0p = &g_h0s[dir][0][0];
    const __nv_bfloat16* __restrict__ h1p = &g_h1s[dir][0][0];
    const __nv_bfloat16* __restrict__ R0p = &g_R0s[dir][0][0];
    const __nv_bfloat16* __restrict__ R1p = &g_R1s[dir][0][0];
    float* __restrict__ red = (float*)(smc + SM_AT);

    for (int step = 0; step < TT; ++step) {
        const int t = dir ? (TT - 1 - step) : step;

        // ================= phase 1 =================
        float A0[4] = {0,0,0,0}, A1[4] = {0,0,0,0}, A2[4] = {0,0,0,0};
        uint4 v0[2], v1[2];
        #pragma unroll
        for (int u = 0; u < 2; ++u) {
            v0[u] = *(const uint4*)(h0p + grow[u] * HH + gseg[u] * 8);
            v1[u] = *(const uint4*)(h1p + grow[u] * HH + gseg[u] * 8);
        }
        #pragma unroll 1
        for (int kb = 0; kb < 8; ++kb) {
            __syncthreads();
            #pragma unroll
            for (int u = 0; u < 2; ++u) {
                *(uint4*)(smc + SM_AT + grow[u] * 272 + gseg[u] * 16)          = v0[u];
                *(uint4*)(smc + SM_AT + AT_STR + grow[u] * 272 + gseg[u] * 16) = v1[u];
            }
            __syncthreads();
            if (kb < 7) {
                #pragma unroll
                for (int u = 0; u < 2; ++u) {
                    v0[u] = *(const uint4*)(h0p + grow[u] * HH + (kb + 1) * 128 + gseg[u] * 8);
                    v1[u] = *(const uint4*)(h1p + grow[u] * HH + (kb + 1) * 128 + gseg[u] * 8);
                }
            }
            #pragma unroll
            for (int ks = 0; ks < 8; ++ks) {
                uint32_t a0[4], a1[4];
                ldmA(a0, smb + SM_AT + aoff1 + ks * 32);
                ldmA(a1, smb + SM_AT + AT_STR + aoff1 + ks * 32);
                uint4 bb = *(const uint4*)&Bf1[((n1 * 64 + kb * 8 + ks) * 32 + lane) * 4];
                mmabf(A0, a0, bb.x, bb.y);
                mmabf(A1, a1, bb.x, bb.y);
                mmabf(A2, a0, bb.z, bb.w);
            }
        }
        {
            const float* __restrict__ xrz = &g_Xrz[dir][t][0][0];
            #pragma unroll
            for (int i = 0; i < 4; ++i) {
                int b  = m1 * 16 + gid + (i >> 1) * 8;
                int cc = n1 * 8 + 2 * tig + (i & 1);
                int jj = c * 32 + cc;
                float pre = A0[i] + A1[i] + A2[i] + xrz[b * (2 * HH) + jj];
                float s = 1.f / (1.f + __expf(-pre));
                if (isR) {
                    float v = s * g_h[dir][b][jj];
                    g_R0s[dir][b][jj] = __float2bfloat16(v);
                    g_R1s[dir][b][jj] = __float2bfloat16(v - bhi(v));
                } else {
                    g_Z[dir][b][jj - HH] = s;
                }
            }
        }
        dir_barrier(dir);

        // ================= phase 2 =================
        float C0[4] = {0,0,0,0}, C1[4] = {0,0,0,0}, C2[4] = {0,0,0,0};
        #pragma unroll
        for (int u = 0; u < 2; ++u) {
            v0[u] = *(const uint4*)(R0p + grow[u] * HH + gseg[u] * 8);
            v1[u] = *(const uint4*)(R1p + grow[u] * HH + gseg[u] * 8);
        }
        #pragma unroll 1
        for (int kb = 0; kb < 8; ++kb) {
            __syncthreads();
            #pragma unroll
            for (int u = 0; u < 2; ++u) {
                *(uint4*)(smc + SM_AT + grow[u] * 272 + gseg[u] * 16)          = v0[u];
                *(uint4*)(smc + SM_AT + AT_STR + grow[u] * 272 + gseg[u] * 16) = v1[u];
            }
            __syncthreads();
            if (kb < 7) {
                #pragma unroll
                for (int u = 0; u < 2; ++u) {
                    v0[u] = *(const uint4*)(R0p + grow[u] * HH + (kb + 1) * 128 + gseg[u] * 8);
                    v1[u] = *(const uint4*)(R1p + grow[u] * HH + (kb + 1) * 128 + gseg[u] * 8);
                }
            }
            if ((kb >> 2) == wk) {
                #pragma unroll
                for (int ks = 0; ks < 8; ++ks) {
                    uint32_t a0[4], a1[4];
                    ldmA(a0, smb + SM_AT + aoff2 + ks * 32);
                    ldmA(a1, smb + SM_AT + AT_STR + aoff2 + ks * 32);
                    uint4 bb = *(const uint4*)&Bf2[((n2 * 64 + kb * 8 + ks) * 32 + lane) * 4];
                    mmabf(C0, a0, bb.x, bb.y);
                    mmabf(C1, a1, bb.x, bb.y);
                    mmabf(C2, a0, bb.z, bb.w);
                }
            }
        }
        __syncthreads();
        if (wk == 1) {
            #pragma unroll
            for (int i = 0; i < 4; ++i) {
                int r  = m2 * 16 + gid + (i >> 1) * 8;
                int cc = n2 * 8 + 2 * tig + (i & 1);
                red[r * 16 + cc] = C0[i] + C1[i] + C2[i];
            }
        }
        __syncthreads();
        if (wk == 0) {
            const float* __restrict__ xh = &g_Xh[dir][t][0][0];
            #pragma unroll
            for (int i = 0; i < 4; ++i) {
                int b  = m2 * 16 + gid + (i >> 1) * 8;
                int cc = n2 * 8 + 2 * tig + (i & 1);
                int j2 = c * 16 + cc;
                float sum = C0[i] + C1[i] + C2[i] + red[b * 16 + cc];
                float htil = tanhf(sum + xh[b * HH + j2]);
                float z    = g_Z[dir][b][j2];
                float hold = g_h[dir][b][j2];
                float hnew = z * htil + (1.f - z) * hold;
                g_h[dir][b][j2] = hnew;
                g_h0s[dir][b][j2] = __float2bfloat16(hnew);
                g_h1s[dir][b][j2] = __float2bfloat16(hnew - bhi(hnew));
                out[(size_t)(b * TT + t) * (2 * HH) + dir * HH + j2] = hnew;
            }
        }
        dir_barrier(dir);
    }
}

// ---------------------------------------------------------------------------
extern "C" void kernel_launch(void* const* d_in, const int* in_sizes, int n_in,
                              void* d_out, int out_size) {
    (void)in_sizes; (void)n_in; (void)out_size;
    const float* x     = (const float*)d_in[0];
    const float* hf0   = (const float*)d_in[1];
    const float* hb0   = (const float*)d_in[2];
    const float* Whr_f = (const float*)d_in[3];
    const float* Wxr_f = (const float*)d_in[4];
    const float* br_f  = (const float*)d_in[5];
    const float* Whz_f = (const float*)d_in[6];
    const float* Wxz_f = (const float*)d_in[7];
    const float* bz_f  = (const float*)d_in[8];
    const float* Whh_f = (const float*)d_in[9];
    const float* Wxh_f = (const float*)d_in[10];
    const float* bh_f  = (const float*)d_in[11];
    const float* Whr_b = (const float*)d_in[12];
    const float* Wxr_b = (const float*)d_in[13];
    const float* br_b  = (const float*)d_in[14];
    const float* Whz_b = (const float*)d_in[15];
    const float* Wxz_b = (const float*)d_in[16];
    const float* bz_b  = (const float*)d_in[17];
    const float* Whh_b = (const float*)d_in[18];
    const float* Wxh_b = (const float*)d_in[19];
    const float* bh_b  = (const float*)d_in[20];
    float* out = (float*)d_out;

    static int smem_set = 0;
    if (!smem_set) {
        cudaFuncSetAttribute(gru_rec_kernel,
                             cudaFuncAttributeMaxDynamicSharedMemorySize,
                             SM_BYTES);
        smem_set = 1;
    }

    wprep_kernel<<<dim3(512, 3, 2), 256>>>(Wxr_f, Wxz_f, Wxh_f, Wxr_b, Wxz_b, Wxh_b);
    inproj_mma_kernel<<<dim3(256, 32, 2), 256>>>(x, br_f, bz_f, bh_f, br_b, bz_b, bh_b);
    gru_rec_kernel<<<2 * NCTA_DIR, 512, SM_BYTES>>>(hf0, hb0,
        Whr_f, Whz_f, Whh_f, Whr_b, Whz_b, Whh_b, out);
}

// round 12
// speedup vs baseline: 2.5569x; 1.0310x over previous
#include <cuda_runtime.h>
#include <cuda_bf16.h>
#include <cstdint>

#define BB 64
#define TT 512
#define II 512
#define HH 1024
#define NCTA_DIR 64

// ---------------- scratch (device globals) ----------------------------------
__device__ float g_Xrz[2][TT][BB][2 * HH];
__device__ float g_Xh [2][TT][BB][HH];
__device__ float g_h  [2][BB][HH];             // master hidden state (fp32)
__device__ float g_Z  [2][BB][HH];
// A-operands stored directly in mma fragment layout:
//   [dir][m-tile(4)][k-frag q(64)][split(2)][lane(32)] -> uint4 (4 regs)
__device__ uint4 g_hf[2][4][64][2][32];
__device__ uint4 g_Rf[2][4][64][2][32];
__device__ uint4 g_Wf[2][3][128][32][32];      // x-weight B-fragments (prep)
__device__ unsigned g_bar_count[2];
__device__ unsigned g_bar_gen[2];

// ---------------- helpers ----------------------------------------------------
__device__ __forceinline__ uint32_t smem_u32(const void* p) {
    uint32_t a;
    asm("{ .reg .u64 t; cvta.to.shared.u64 t, %1; cvt.u32.u64 %0, t; }"
        : "=r"(a) : "l"(p));
    return a;
}
__device__ __forceinline__ void mmabf(float* d, const uint32_t* a,
                                      uint32_t b0, uint32_t b1) {
    asm volatile("mma.sync.aligned.m16n8k16.row.col.f32.bf16.bf16.f32 "
                 "{%0,%1,%2,%3},{%4,%5,%6,%7},{%8,%9},{%0,%1,%2,%3};"
                 : "+f"(d[0]), "+f"(d[1]), "+f"(d[2]), "+f"(d[3])
                 : "r"(a[0]), "r"(a[1]), "r"(a[2]), "r"(a[3]), "r"(b0), "r"(b1));
}
__device__ __forceinline__ uint32_t pk(float a, float b) {
    __nv_bfloat16 l = __float2bfloat16(a), h = __float2bfloat16(b);
    unsigned short ls = *(unsigned short*)&l, hs = *(unsigned short*)&h;
    return (uint32_t)ls | ((uint32_t)hs << 16);
}
__device__ __forceinline__ float bhi(float x) {
    return __bfloat162float(__float2bfloat16(x));
}

// ------------- per-direction software grid barrier ---------------------------
__device__ __forceinline__ void dir_barrier(int dir) {
    __syncthreads();
    if (threadIdx.x == 0) {
        volatile unsigned* vgen = (volatile unsigned*)&g_bar_gen[dir];
        unsigned my = *vgen;
        __threadfence();
        unsigned a = atomicAdd(&g_bar_count[dir], 1u);
        if (a == NCTA_DIR - 1) {
            g_bar_count[dir] = 0;
            __threadfence();
            atomicAdd(&g_bar_gen[dir], 1u);
        } else {
            while (*vgen == my) { }
            __threadfence();
        }
    }
    __syncthreads();
}

// ---------------- weight-fragment prep for inproj (unchanged) ----------------
__global__ void __launch_bounds__(256) wprep_kernel(
    const float* __restrict__ Wr_f, const float* __restrict__ Wz_f, const float* __restrict__ Wh_f,
    const float* __restrict__ Wr_b, const float* __restrict__ Wz_b, const float* __restrict__ Wh_b)
{
    const int gate = blockIdx.y, dir = blockIdx.z;
    const float* W;
    if (dir == 0) W = (gate == 0) ? Wr_f : (gate == 1) ? Wz_f : Wh_f;
    else          W = (gate == 0) ? Wr_b : (gate == 1) ? Wz_b : Wh_b;

    int e = blockIdx.x * 256 + threadIdx.x;
    int lane = e & 31, q = (e >> 5) & 31, nt = e >> 10;
    int ge = lane >> 2, te = lane & 3;
    int j = nt * 8 + ge;
    uint32_t fr[4];
    #pragma unroll
    for (int breg = 0; breg < 2; ++breg) {
        int k0 = q * 16 + breg * 8 + 2 * te;
        float f0 = W[k0 * HH + j], f1 = W[(k0 + 1) * HH + j];
        fr[breg]     = pk(bhi(f0), bhi(f1));
        fr[2 + breg] = pk(f0 - bhi(f0), f1 - bhi(f1));
    }
    g_Wf[dir][gate][nt][q][lane] = make_uint4(fr[0], fr[1], fr[2], fr[3]);
}

// ---------------- inproj on tensor cores (unchanged from R11) ----------------
__global__ void __launch_bounds__(256) inproj_mma_kernel(
    const float* __restrict__ x,
    const float* __restrict__ br_f, const float* __restrict__ bz_f, const float* __restrict__ bh_f,
    const float* __restrict__ br_b, const float* __restrict__ bz_b, const float* __restrict__ bh_b)
{
    __shared__ char xs0[128 * 144];
    __shared__ char xs1[128 * 144];
    const uint32_t s0 = smem_u32(xs0), s1 = smem_u32(xs1);

    const int mTile = blockIdx.x, cTile = blockIdx.y, dir = blockIdx.z;
    const int tid = threadIdx.x, w = tid >> 5, lane = tid & 31;
    const int gid = lane >> 2, tig = lane & 3;
    const int wm = w >> 1, wn = w & 1;

    const float* bias[3] = { dir ? br_b : br_f, dir ? bz_b : bz_f, dir ? bh_b : bh_f };

    float C[3][2][2][4];
    #pragma unroll
    for (int g = 0; g < 3; ++g)
        #pragma unroll
        for (int mt = 0; mt < 2; ++mt)
            #pragma unroll
            for (int nt = 0; nt < 2; ++nt)
                #pragma unroll
                for (int i = 0; i < 4; ++i) C[g][mt][nt][i] = 0.f;

    const float* xb = x + (size_t)(mTile * 128) * II;

    #pragma unroll 1
    for (int kb = 0; kb < 8; ++kb) {
        __syncthreads();
        #pragma unroll
        for (int u = 0; u < 8; ++u) {
            int e = tid + 256 * u;
            int row = e >> 4, q4 = e & 15;
            float4 v = *(const float4*)(xb + row * II + kb * 64 + q4 * 4);
            *(uint2*)(xs0 + row * 144 + q4 * 8) =
                make_uint2(pk(bhi(v.x), bhi(v.y)), pk(bhi(v.z), bhi(v.w)));
            *(uint2*)(xs1 + row * 144 + q4 * 8) =
                make_uint2(pk(v.x - bhi(v.x), v.y - bhi(v.y)),
                           pk(v.z - bhi(v.z), v.w - bhi(v.w)));
        }
        __syncthreads();
        #pragma unroll
        for (int ks = 0; ks < 4; ++ks) {
            uint32_t a0[2][4], a1[2][4];
            #pragma unroll
            for (int mt = 0; mt < 2; ++mt) {
                uint32_t ao = (uint32_t)((wm * 32 + mt * 16 + (lane & 15)) * 144
                                         + (lane >> 4) * 16 + ks * 32);
                asm volatile("ldmatrix.sync.aligned.m8n8.x4.shared.b16 {%0,%1,%2,%3}, [%4];"
                             : "=r"(a0[mt][0]), "=r"(a0[mt][1]), "=r"(a0[mt][2]), "=r"(a0[mt][3])
                             : "r"(s0 + ao));
                asm volatile("ldmatrix.sync.aligned.m8n8.x4.shared.b16 {%0,%1,%2,%3}, [%4];"
                             : "=r"(a1[mt][0]), "=r"(a1[mt][1]), "=r"(a1[mt][2]), "=r"(a1[mt][3])
                             : "r"(s1 + ao));
            }
            #pragma unroll
            for (int g = 0; g < 3; ++g) {
                #pragma unroll
                for (int nt = 0; nt < 2; ++nt) {
                    uint4 bb = g_Wf[dir][g][cTile * 4 + wn * 2 + nt][kb * 4 + ks][lane];
                    #pragma unroll
                    for (int mt = 0; mt < 2; ++mt) {
                        mmabf(C[g][mt][nt], a0[mt], bb.x, bb.y);
                        mmabf(C[g][mt][nt], a1[mt], bb.x, bb.y);
                        mmabf(C[g][mt][nt], a0[mt], bb.z, bb.w);
                    }
                }
            }
        }
    }
    #pragma unroll
    for (int g = 0; g < 3; ++g)
        #pragma unroll
        for (int mt = 0; mt < 2; ++mt)
            #pragma unroll
            for (int nt = 0; nt < 2; ++nt)
                #pragma unroll
                for (int i = 0; i < 4; ++i) {
                    int row = mTile * 128 + wm * 32 + mt * 16 + gid + (i >> 1) * 8;
                    int j   = cTile * 32 + wn * 16 + nt * 8 + 2 * tig + (i & 1);
                    int b = row >> 9, t = row & (TT - 1);
                    float v = C[g][mt][nt][i] + bias[g][j];
                    if (g == 0)      g_Xrz[dir][t][b][j]      = v;
                    else if (g == 1) g_Xrz[dir][t][b][HH + j] = v;
                    else             g_Xh [dir][t][b][j]      = v;
                }
}

// ---------------- persistent tensor-core recurrence --------------------------
// A operands live in GLOBAL fragment layout (g_hf/g_Rf): GEMMs do coalesced
// LDG.128 + LDS.128(B) + HMMA with ZERO staging syncs. SMEM: Bf1|Bf2|red.
#define SM_BF1 0
#define SM_BF2 131072
#define SM_RED 196608
#define SM_BYTES 200704

__global__ void __launch_bounds__(512) gru_rec_kernel(
    const float* __restrict__ hf0, const float* __restrict__ hb0,
    const float* __restrict__ Whr_f, const float* __restrict__ Whz_f, const float* __restrict__ Whh_f,
    const float* __restrict__ Whr_b, const float* __restrict__ Whz_b, const float* __restrict__ Whh_b,
    float* __restrict__ out)
{
    extern __shared__ char smc[];
    uint32_t* Bf1 = (uint32_t*)(smc + SM_BF1);
    uint32_t* Bf2 = (uint32_t*)(smc + SM_BF2);
    float* red = (float*)(smc + SM_RED);

    const int tid = threadIdx.x;
    const int w = tid >> 5, lane = tid & 31;
    const int gid = lane >> 2, tig = lane & 3;
    const int dir = blockIdx.x >> 6;
    const int c   = blockIdx.x & 63;
    const bool isR = (c < 32);

    const float* __restrict__ Whr = dir ? Whr_b : Whr_f;
    const float* __restrict__ Whz = dir ? Whz_b : Whz_f;
    const float* __restrict__ Whh = dir ? Whh_b : Whh_f;
    const float* __restrict__ h0in = dir ? hb0 : hf0;
    const float* __restrict__ Wg  = isR ? Whr : Whz;

    // ---- one-time: recurrent weight splits into B-fragment SMEM ----
    for (int e = tid; e < 8192; e += 512) {
        int le = e & 31, q = (e >> 5) & 63, n = e >> 11;
        int ge = le >> 2, te = le & 3;
        int jw = (c * 32 + n * 8 + ge) & (HH - 1);
        #pragma unroll
        for (int breg = 0; breg < 2; ++breg) {
            int k0 = q * 16 + breg * 8 + 2 * te;
            float f0 = Wg[k0 * HH + jw], f1 = Wg[(k0 + 1) * HH + jw];
            Bf1[e * 4 + breg]     = pk(bhi(f0), bhi(f1));
            Bf1[e * 4 + 2 + breg] = pk(f0 - bhi(f0), f1 - bhi(f1));
        }
    }
    for (int e = tid; e < 4096; e += 512) {
        int le = e & 31, q = (e >> 5) & 63, n = (e >> 11) & 1;
        int ge = le >> 2, te = le & 3;
        int j2w = c * 16 + n * 8 + ge;
        #pragma unroll
        for (int breg = 0; breg < 2; ++breg) {
            int k0 = q * 16 + breg * 8 + 2 * te;
            float f0 = Whh[k0 * HH + j2w], f1 = Whh[(k0 + 1) * HH + j2w];
            Bf2[e * 4 + breg]     = pk(bhi(f0), bhi(f1));
            Bf2[e * 4 + 2 + breg] = pk(f0 - bhi(f0), f1 - bhi(f1));
        }
    }
    // ---- init master h + h fragments (every replay: deterministic) ----
    {
        int base = c * 1024;
        #pragma unroll
        for (int u = 0; u < 2; ++u) {
            int idx = base + u * 512 + tid;
            (&g_h[dir][0][0])[idx] = h0in[idx];
        }
        for (int e = tid; e < 4 * 64 * 2 * 32; e += 512) {
            int le = e & 31, s = (e >> 5) & 1, q = (e >> 6) & 63, m = e >> 12;
            uint32_t wds[4];
            #pragma unroll
            for (int r = 0; r < 4; ++r) {
                int row = m * 16 + (le >> 2) + 8 * (r & 1);
                int col = q * 16 + 2 * (le & 3) + 8 * (r >> 1);
                float v0 = h0in[row * HH + col], v1 = h0in[row * HH + col + 1];
                wds[r] = s ? pk(v0 - bhi(v0), v1 - bhi(v1)) : pk(v0, v1);
            }
            g_hf[dir][m][q][s][le] = make_uint4(wds[0], wds[1], wds[2], wds[3]);
        }
    }
    dir_barrier(dir);

    const int m1 = w >> 2, n1 = w & 3;          // phase1: 4M x 4N, full K
    const int wk = w >> 3, w8 = w & 7;          // phase2: 4M x 2N x 2K-split
    const int m2 = w8 >> 1, n2 = w8 & 1;

    for (int step = 0; step < TT; ++step) {
        const int t = dir ? (TT - 1 - step) : step;

        // ================= phase 1: [R|Z] = sigmoid(h@W + x) =============
        float A0[4] = {0,0,0,0}, A1[4] = {0,0,0,0}, A2[4] = {0,0,0,0};
        #pragma unroll 1
        for (int qb = 0; qb < 8; ++qb) {
            #pragma unroll
            for (int qi = 0; qi < 8; ++qi) {
                const int q = qb * 8 + qi;
                uint4 s0 = g_hf[dir][m1][q][0][lane];
                uint4 s1 = g_hf[dir][m1][q][1][lane];
                uint4 bb = *(const uint4*)&Bf1[((n1 * 64 + q) * 32 + lane) * 4];
                mmabf(A0, (const uint32_t*)&s0, bb.x, bb.y);
                mmabf(A1, (const uint32_t*)&s1, bb.x, bb.y);
                mmabf(A2, (const uint32_t*)&s0, bb.z, bb.w);
            }
        }
        {
            const float* __restrict__ xrz = &g_Xrz[dir][t][0][0];
            float v[4];
            #pragma unroll
            for (int i = 0; i < 4; ++i) {
                int b  = m1 * 16 + gid + (i >> 1) * 8;
                int cc = n1 * 8 + 2 * tig + (i & 1);
                int jj = c * 32 + cc;
                float pre = A0[i] + A1[i] + A2[i] + xrz[b * (2 * HH) + jj];
                float s = 1.f / (1.f + __expf(-pre));
                if (isR) v[i] = s * g_h[dir][b][jj];
                else     g_Z[dir][b][jj - HH] = s;
            }
            if (isR) {   // write R*h fragments: one STG.64 per split
                int q = c * 2 + (n1 >> 1);
                int off = (n1 & 1) * 8;
                *(uint2*)((char*)&g_Rf[dir][m1][q][0][lane] + off) =
                    make_uint2(pk(v[0], v[1]), pk(v[2], v[3]));
                *(uint2*)((char*)&g_Rf[dir][m1][q][1][lane] + off) =
                    make_uint2(pk(v[0] - bhi(v[0]), v[1] - bhi(v[1])),
                               pk(v[2] - bhi(v[2]), v[3] - bhi(v[3])));
            }
        }
        dir_barrier(dir);

        // ========== phase 2: h = Z*tanh(RH@Whh + xh) + (1-Z)*h ===========
        float C0[4] = {0,0,0,0}, C1[4] = {0,0,0,0}, C2[4] = {0,0,0,0};
        #pragma unroll 1
        for (int qb = 0; qb < 4; ++qb) {
            #pragma unroll
            for (int qi = 0; qi < 8; ++qi) {
                const int q = wk * 32 + qb * 8 + qi;
                uint4 s0 = g_Rf[dir][m2][q][0][lane];
                uint4 s1 = g_Rf[dir][m2][q][1][lane];
                uint4 bb = *(const uint4*)&Bf2[((n2 * 64 + q) * 32 + lane) * 4];
                mmabf(C0, (const uint32_t*)&s0, bb.x, bb.y);
                mmabf(C1, (const uint32_t*)&s1, bb.x, bb.y);
                mmabf(C2, (const uint32_t*)&s0, bb.z, bb.w);
            }
        }
        __syncthreads();
        if (wk == 1) {
            #pragma unroll
            for (int i = 0; i < 4; ++i) {
                int r  = m2 * 16 + gid + (i >> 1) * 8;
                int cc = n2 * 8 + 2 * tig + (i & 1);
                red[r * 16 + cc] = C0[i] + C1[i] + C2[i];
            }
        }
        __syncthreads();
        if (wk == 0) {
            const float* __restrict__ xh = &g_Xh[dir][t][0][0];
            float hn[4];
            #pragma unroll
            for (int i = 0; i < 4; ++i) {
                int b  = m2 * 16 + gid + (i >> 1) * 8;
                int cc = n2 * 8 + 2 * tig + (i & 1);
                int j2 = c * 16 + cc;
                float sum = C0[i] + C1[i] + C2[i] + red[b * 16 + cc];
                float htil = tanhf(sum + xh[b * HH + j2]);
                float z    = g_Z[dir][b][j2];
                float hold = g_h[dir][b][j2];
                float hnew = z * htil + (1.f - z) * hold;
                g_h[dir][b][j2] = hnew;
                out[(size_t)(b * TT + t) * (2 * HH) + dir * HH + j2] = hnew;
                hn[i] = hnew;
            }
            // write h fragments: one STG.64 per split
            int off = n2 * 8;
            *(uint2*)((char*)&g_hf[dir][m2][c][0][lane] + off) =
                make_uint2(pk(hn[0], hn[1]), pk(hn[2], hn[3]));
            *(uint2*)((char*)&g_hf[dir][m2][c][1][lane] + off) =
                make_uint2(pk(hn[0] - bhi(hn[0]), hn[1] - bhi(hn[1])),
                           pk(hn[2] - bhi(hn[2]), hn[3] - bhi(hn[3])));
        }
        dir_barrier(dir);
    }
}

// ---------------------------------------------------------------------------
extern "C" void kernel_launch(void* const* d_in, const int* in_sizes, int n_in,
                              void* d_out, int out_size) {
    (void)in_sizes; (void)n_in; (void)out_size;
    const float* x     = (const float*)d_in[0];
    const float* hf0   = (const float*)d_in[1];
    const float* hb0   = (const float*)d_in[2];
    const float* Whr_f = (const float*)d_in[3];
    const float* Wxr_f = (const float*)d_in[4];
    const float* br_f  = (const float*)d_in[5];
    const float* Whz_f = (const float*)d_in[6];
    const float* Wxz_f = (const float*)d_in[7];
    const float* bz_f  = (const float*)d_in[8];
    const float* Whh_f = (const float*)d_in[9];
    const float* Wxh_f = (const float*)d_in[10];
    const float* bh_f  = (const float*)d_in[11];
    const float* Whr_b = (const float*)d_in[12];
    const float* Wxr_b = (const float*)d_in[13];
    const float* br_b  = (const float*)d_in[14];
    const float* Whz_b = (const float*)d_in[15];
    const float* Wxz_b = (const float*)d_in[16];
    const float* bz_b  = (const float*)d_in[17];
    const float* Whh_b = (const float*)d_in[18];
    const float* Wxh_b = (const float*)d_in[19];
    const float* bh_b  = (const float*)d_in[20];
    float* out = (float*)d_out;

    static int smem_set = 0;
    if (!smem_set) {
        cudaFuncSetAttribute(gru_rec_kernel,
                             cudaFuncAttributeMaxDynamicSharedMemorySize,
                             SM_BYTES);
        smem_set = 1;
    }

    wprep_kernel<<<dim3(512, 3, 2), 256>>>(Wxr_f, Wxz_f, Wxh_f, Wxr_b, Wxz_b, Wxh_b);
    inproj_mma_kernel<<<dim3(256, 32, 2), 256>>>(x, br_f, bz_f, bh_f, br_b, bz_b, bh_b);
    gru_rec_kernel<<<2 * NCTA_DIR, 512, SM_BYTES>>>(hf0, hb0,
        Whr_f, Whz_f, Whh_f, Whr_b, Whz_b, Whh_b, out);
}

// round 16
// speedup vs baseline: 2.9412x; 1.1503x over previous
#include <cuda_runtime.h>
#include <cuda_bf16.h>
#include <cstdint>

#define BB 64
#define TT 512
#define II 512
#define HH 1024
#define NCTA_DIR 64

// ---------------- scratch (device globals) ----------------------------------
__device__ float g_Xrz[2][TT][BB][2 * HH];
__device__ float g_Xh [2][TT][BB][HH];
__device__ float g_hm [2][2][BB][HH];          // master h, double-buffered [parity]
__device__ float g_Z  [2][BB][HH];
// A-operand fragments: [parity][dir][m-tile(4)][q(64)][split(2)][lane(32)]
__device__ uint4 g_hf[2][2][4][64][2][32];
__device__ uint4 g_Rf[2][4][64][2][32];
__device__ uint4 g_Wf[2][3][128][32][32];      // x-weight B-fragments (prep)
// data-ready flags, 32B padded; ALWAYS 0 at kernel entry (reset at kernel exit)
__device__ unsigned g_hflag [2][64][8];
__device__ unsigned g_rzflag[2][64][8];
__device__ unsigned g_bar_count[2];
__device__ unsigned g_bar_gen[2];

// ---------------- helpers ----------------------------------------------------
__device__ __forceinline__ uint32_t smem_u32(const void* p) {
    uint32_t a;
    asm("{ .reg .u64 t; cvta.to.shared.u64 t, %1; cvt.u32.u64 %0, t; }"
        : "=r"(a) : "l"(p));
    return a;
}
__device__ __forceinline__ void mmabf(float* d, const uint32_t* a,
                                      uint32_t b0, uint32_t b1) {
    asm volatile("mma.sync.aligned.m16n8k16.row.col.f32.bf16.bf16.f32 "
                 "{%0,%1,%2,%3},{%4,%5,%6,%7},{%8,%9},{%0,%1,%2,%3};"
                 : "+f"(d[0]), "+f"(d[1]), "+f"(d[2]), "+f"(d[3])
                 : "r"(a[0]), "r"(a[1]), "r"(a[2]), "r"(a[3]), "r"(b0), "r"(b1));
}
__device__ __forceinline__ uint32_t pk(float a, float b) {
    __nv_bfloat16 l = __float2bfloat16(a), h = __float2bfloat16(b);
    unsigned short ls = *(unsigned short*)&l, hs = *(unsigned short*)&h;
    return (uint32_t)ls | ((uint32_t)hs << 16);
}
__device__ __forceinline__ float bhi(float x) {
    return __bfloat162float(__float2bfloat16(x));
}
__device__ __forceinline__ void stcg_u32(unsigned* p, unsigned v) {
    asm volatile("st.global.cg.u32 [%0], %1;" :: "l"(p), "r"(v) : "memory");
}
// MORALLY-STRONG flag ops (the R13-R15 bug: weak .cg flag ops create no
// synchronizes-with edge in the PTX memory model, fences notwithstanding).
__device__ __forceinline__ unsigned ldacq_u32(const unsigned* p) {
    unsigned v;
    asm volatile("ld.acquire.gpu.global.u32 %0, [%1];" : "=r"(v) : "l"(p) : "memory");
    return v;
}
__device__ __forceinline__ void publish_flag(unsigned* slot, unsigned val) {
    asm volatile("st.release.gpu.global.u32 [%0], %1;" :: "l"(slot), "r"(val) : "memory");
}
// warp 0 spins with ACQUIRE loads on 2 flags/lane; CTA reconverges at barrier.
__device__ __forceinline__ void wait_flags(const unsigned (*flags)[8], int tid,
                                           unsigned tgt) {
    if (tid < 32) {
        const unsigned* f0 = &flags[tid][0];
        const unsigned* f1 = &flags[tid + 32][0];
        while (ldacq_u32(f0) < tgt) { }
        while (ldacq_u32(f1) < tgt) { }
    }
    __syncthreads();
}
// atomic rendezvous (proven R3-R12) — used ONLY twice at end of run
__device__ __forceinline__ void dir_barrier(int dir) {
    __syncthreads();
    if (threadIdx.x == 0) {
        volatile unsigned* vgen = (volatile unsigned*)&g_bar_gen[dir];
        unsigned my = *vgen;
        __threadfence();
        unsigned a = atomicAdd(&g_bar_count[dir], 1u);
        if (a == NCTA_DIR - 1) {
            g_bar_count[dir] = 0;
            __threadfence();
            atomicAdd(&g_bar_gen[dir], 1u);
        } else {
            while (*vgen == my) { }
            __threadfence();
        }
    }
    __syncthreads();
}

// ---------------- weight-fragment prep for inproj (unchanged) ----------------
__global__ void __launch_bounds__(256) wprep_kernel(
    const float* __restrict__ Wr_f, const float* __restrict__ Wz_f, const float* __restrict__ Wh_f,
    const float* __restrict__ Wr_b, const float* __restrict__ Wz_b, const float* __restrict__ Wh_b)
{
    const int gate = blockIdx.y, dir = blockIdx.z;
    const float* W;
    if (dir == 0) W = (gate == 0) ? Wr_f : (gate == 1) ? Wz_f : Wh_f;
    else          W = (gate == 0) ? Wr_b : (gate == 1) ? Wz_b : Wh_b;

    int e = blockIdx.x * 256 + threadIdx.x;
    int lane = e & 31, q = (e >> 5) & 31, nt = e >> 10;
    int ge = lane >> 2, te = lane & 3;
    int j = nt * 8 + ge;
    uint32_t fr[4];
    #pragma unroll
    for (int breg = 0; breg < 2; ++breg) {
        int k0 = q * 16 + breg * 8 + 2 * te;
        float f0 = W[k0 * HH + j], f1 = W[(k0 + 1) * HH + j];
        fr[breg]     = pk(bhi(f0), bhi(f1));
        fr[2 + breg] = pk(f0 - bhi(f0), f1 - bhi(f1));
    }
    g_Wf[dir][gate][nt][q][lane] = make_uint4(fr[0], fr[1], fr[2], fr[3]);
}

// ---------------- inproj on tensor cores (unchanged from R12) ----------------
__global__ void __launch_bounds__(256) inproj_mma_kernel(
    const float* __restrict__ x,
    const float* __restrict__ br_f, const float* __restrict__ bz_f, const float* __restrict__ bh_f,
    const float* __restrict__ br_b, const float* __restrict__ bz_b, const float* __restrict__ bh_b)
{
    __shared__ char xs0[128 * 144];
    __shared__ char xs1[128 * 144];
    const uint32_t s0 = smem_u32(xs0), s1 = smem_u32(xs1);

    const int mTile = blockIdx.x, cTile = blockIdx.y, dir = blockIdx.z;
    const int tid = threadIdx.x, w = tid >> 5, lane = tid & 31;
    const int gid = lane >> 2, tig = lane & 3;
    const int wm = w >> 1, wn = w & 1;

    const float* bias[3] = { dir ? br_b : br_f, dir ? bz_b : bz_f, dir ? bh_b : bh_f };

    float C[3][2][2][4];
    #pragma unroll
    for (int g = 0; g < 3; ++g)
        #pragma unroll
        for (int mt = 0; mt < 2; ++mt)
            #pragma unroll
            for (int nt = 0; nt < 2; ++nt)
                #pragma unroll
                for (int i = 0; i < 4; ++i) C[g][mt][nt][i] = 0.f;

    const float* xb = x + (size_t)(mTile * 128) * II;

    #pragma unroll 1
    for (int kb = 0; kb < 8; ++kb) {
        __syncthreads();
        #pragma unroll
        for (int u = 0; u < 8; ++u) {
            int e = tid + 256 * u;
            int row = e >> 4, q4 = e & 15;
            float4 v = *(const float4*)(xb + row * II + kb * 64 + q4 * 4);
            *(uint2*)(xs0 + row * 144 + q4 * 8) =
                make_uint2(pk(bhi(v.x), bhi(v.y)), pk(bhi(v.z), bhi(v.w)));
            *(uint2*)(xs1 + row * 144 + q4 * 8) =
                make_uint2(pk(v.x - bhi(v.x), v.y - bhi(v.y)),
                           pk(v.z - bhi(v.z), v.w - bhi(v.w)));
        }
        __syncthreads();
        #pragma unroll
        for (int ks = 0; ks < 4; ++ks) {
            uint32_t a0[2][4], a1[2][4];
            #pragma unroll
            for (int mt = 0; mt < 2; ++mt) {
                uint32_t ao = (uint32_t)((wm * 32 + mt * 16 + (lane & 15)) * 144
                                         + (lane >> 4) * 16 + ks * 32);
                asm volatile("ldmatrix.sync.aligned.m8n8.x4.shared.b16 {%0,%1,%2,%3}, [%4];"
                             : "=r"(a0[mt][0]), "=r"(a0[mt][1]), "=r"(a0[mt][2]), "=r"(a0[mt][3])
                             : "r"(s0 + ao));
                asm volatile("ldmatrix.sync.aligned.m8n8.x4.shared.b16 {%0,%1,%2,%3}, [%4];"
                             : "=r"(a1[mt][0]), "=r"(a1[mt][1]), "=r"(a1[mt][2]), "=r"(a1[mt][3])
                             : "r"(s1 + ao));
            }
            #pragma unroll
            for (int g = 0; g < 3; ++g) {
                #pragma unroll
                for (int nt = 0; nt < 2; ++nt) {
                    uint4 bb = g_Wf[dir][g][cTile * 4 + wn * 2 + nt][kb * 4 + ks][lane];
                    #pragma unroll
                    for (int mt = 0; mt < 2; ++mt) {
                        mmabf(C[g][mt][nt], a0[mt], bb.x, bb.y);
                        mmabf(C[g][mt][nt], a1[mt], bb.x, bb.y);
                        mmabf(C[g][mt][nt], a0[mt], bb.z, bb.w);
                    }
                }
            }
        }
    }
    #pragma unroll
    for (int g = 0; g < 3; ++g)
        #pragma unroll
        for (int mt = 0; mt < 2; ++mt)
            #pragma unroll
            for (int nt = 0; nt < 2; ++nt)
                #pragma unroll
                for (int i = 0; i < 4; ++i) {
                    int row = mTile * 128 + wm * 32 + mt * 16 + gid + (i >> 1) * 8;
                    int j   = cTile * 32 + wn * 16 + nt * 8 + 2 * tig + (i & 1);
                    int b = row >> 9, t = row & (TT - 1);
                    float v = C[g][mt][nt][i] + bias[g][j];
                    if (g == 0)      g_Xrz[dir][t][b][j]      = v;
                    else if (g == 1) g_Xrz[dir][t][b][HH + j] = v;
                    else             g_Xh [dir][t][b][j]      = v;
                }
}

// ---------------- persistent dataflow recurrence ------------------------------
// Flags 0 at entry (reset at exit): init h-flag=1; step s: rz=1+s, h=2+s.
#define SM_BF1 0
#define SM_BF2 131072
#define SM_RED 196608
#define SM_BYTES 200704

__global__ void __launch_bounds__(512) gru_rec_kernel(
    const float* __restrict__ hf0, const float* __restrict__ hb0,
    const float* __restrict__ Whr_f, const float* __restrict__ Whz_f, const float* __restrict__ Whh_f,
    const float* __restrict__ Whr_b, const float* __restrict__ Whz_b, const float* __restrict__ Whh_b,
    float* __restrict__ out)
{
    extern __shared__ char smc[];
    uint32_t* Bf1 = (uint32_t*)(smc + SM_BF1);
    uint32_t* Bf2 = (uint32_t*)(smc + SM_BF2);
    float* red = (float*)(smc + SM_RED);

    const int tid = threadIdx.x;
    const int w = tid >> 5, lane = tid & 31;
    const int gid = lane >> 2, tig = lane & 3;
    const int dir = blockIdx.x >> 6;
    const int c   = blockIdx.x & 63;
    const bool isR = (c < 32);

    const float* __restrict__ Whr = dir ? Whr_b : Whr_f;
    const float* __restrict__ Whz = dir ? Whz_b : Whz_f;
    const float* __restrict__ Whh = dir ? Whh_b : Whh_f;
    const float* __restrict__ h0in = dir ? hb0 : hf0;
    const float* __restrict__ Wg  = isR ? Whr : Whz;

    // ---- one-time: recurrent weight splits into B-fragment SMEM ----
    for (int e = tid; e < 8192; e += 512) {
        int le = e & 31, q = (e >> 5) & 63, n = e >> 11;
        int ge = le >> 2, te = le & 3;
        int jw = (c * 32 + n * 8 + ge) & (HH - 1);
        #pragma unroll
        for (int breg = 0; breg < 2; ++breg) {
            int k0 = q * 16 + breg * 8 + 2 * te;
            float f0 = Wg[k0 * HH + jw], f1 = Wg[(k0 + 1) * HH + jw];
            Bf1[e * 4 + breg]     = pk(bhi(f0), bhi(f1));
            Bf1[e * 4 + 2 + breg] = pk(f0 - bhi(f0), f1 - bhi(f1));
        }
    }
    for (int e = tid; e < 4096; e += 512) {
        int le = e & 31, q = (e >> 5) & 63, n = (e >> 11) & 1;
        int ge = le >> 2, te = le & 3;
        int j2w = c * 16 + n * 8 + ge;
        #pragma unroll
        for (int breg = 0; breg < 2; ++breg) {
            int k0 = q * 16 + breg * 8 + 2 * te;
            float f0 = Whh[k0 * HH + j2w], f1 = Whh[(k0 + 1) * HH + j2w];
            Bf2[e * 4 + breg]     = pk(bhi(f0), bhi(f1));
            Bf2[e * 4 + 2 + breg] = pk(f0 - bhi(f0), f1 - bhi(f1));
        }
    }

    // ---- init: publish ONLY this CTA's h chunk (cols c*16 .. c*16+15) ----
    for (int e = tid; e < 1024; e += 512) {
        int row = e >> 4, col = c * 16 + (e & 15);
        float v = h0in[row * HH + col];
        asm volatile("st.global.cg.f32 [%0], %1;"
                     :: "l"(&g_hm[0][dir][row][col]), "f"(v) : "memory");
    }
    if (tid < 256) {
        int le = tid & 31, s = (tid >> 5) & 1, m = tid >> 6;
        uint32_t wds[4];
        #pragma unroll
        for (int r = 0; r < 4; ++r) {
            int row = m * 16 + (le >> 2) + 8 * (r & 1);
            int col = c * 16 + 2 * (le & 3) + 8 * (r >> 1);
            float v0 = h0in[row * HH + col], v1 = h0in[row * HH + col + 1];
            wds[r] = s ? pk(v0 - bhi(v0), v1 - bhi(v1)) : pk(v0, v1);
        }
        asm volatile("st.global.cg.v4.u32 [%0], {%1,%2,%3,%4};"
                     :: "l"(&g_hf[0][dir][m][c][s][tid & 31]),
                        "r"(wds[0]), "r"(wds[1]), "r"(wds[2]), "r"(wds[3]) : "memory");
    }
    __syncthreads();
    if (tid == 0) publish_flag(&g_hflag[dir][c][0], 1u);

    const int m1 = w >> 2, n1 = w & 3;          // phase1: 4M x 4N, full K
    const int wk = w >> 3, w8 = w & 7;          // phase2: 4M x 2N x 2K-split
    const int m2 = w8 >> 1, n2 = w8 & 1;

    for (int step = 0; step < TT; ++step) {
        const int t = dir ? (TT - 1 - step) : step;
        const int pcur = step & 1, pnxt = (step + 1) & 1;

        // ============ phase 1: wait h[step], GEMM, publish R/Z ============
        wait_flags(g_hflag[dir], tid, 1u + step);

        float A0[4] = {0,0,0,0}, A1[4] = {0,0,0,0}, A2[4] = {0,0,0,0};
        #pragma unroll 1
        for (int qb = 0; qb < 8; ++qb) {
            #pragma unroll
            for (int qi = 0; qi < 8; ++qi) {
                const int q = qb * 8 + qi;
                uint4 s0 = __ldcg(&g_hf[pcur][dir][m1][q][0][lane]);
                uint4 s1 = __ldcg(&g_hf[pcur][dir][m1][q][1][lane]);
                uint4 bb = *(const uint4*)&Bf1[((n1 * 64 + q) * 32 + lane) * 4];
                mmabf(A0, (const uint32_t*)&s0, bb.x, bb.y);
                mmabf(A1, (const uint32_t*)&s1, bb.x, bb.y);
                mmabf(A2, (const uint32_t*)&s0, bb.z, bb.w);
            }
        }
        {
            const float* __restrict__ xrz = &g_Xrz[dir][t][0][0];
            float v[4];
            #pragma unroll
            for (int i = 0; i < 4; ++i) {
                int b  = m1 * 16 + gid + (i >> 1) * 8;
                int cc = n1 * 8 + 2 * tig + (i & 1);
                int jj = c * 32 + cc;
                float pre = A0[i] + A1[i] + A2[i] + xrz[b * (2 * HH) + jj];
                float s = 1.f / (1.f + __expf(-pre));
                if (isR) v[i] = s * __ldcg(&g_hm[pcur][dir][b][jj]);
                else {
                    asm volatile("st.global.cg.f32 [%0], %1;"
                                 :: "l"(&g_Z[dir][b][jj - HH]), "f"(s) : "memory");
                }
            }
            if (isR) {
                int q = c * 2 + (n1 >> 1);
                int off = (n1 & 1) * 8;
                uint2 u0 = make_uint2(pk(v[0], v[1]), pk(v[2], v[3]));
                uint2 u1 = make_uint2(pk(v[0] - bhi(v[0]), v[1] - bhi(v[1])),
                                      pk(v[2] - bhi(v[2]), v[3] - bhi(v[3])));
                asm volatile("st.global.cg.v2.u32 [%0], {%1,%2};"
                             :: "l"((char*)&g_Rf[dir][m1][q][0][lane] + off),
                                "r"(u0.x), "r"(u0.y) : "memory");
                asm volatile("st.global.cg.v2.u32 [%0], {%1,%2};"
                             :: "l"((char*)&g_Rf[dir][m1][q][1][lane] + off),
                                "r"(u1.x), "r"(u1.y) : "memory");
            }
        }
        __syncthreads();
        if (tid == 0) publish_flag(&g_rzflag[dir][c][0], 1u + step);

        // ============ phase 2: wait R/Z[step], GEMM, publish h[step+1] ====
        wait_flags(g_rzflag[dir], tid, 1u + step);

        float C0[4] = {0,0,0,0}, C1[4] = {0,0,0,0}, C2[4] = {0,0,0,0};
        #pragma unroll 1
        for (int qb = 0; qb < 4; ++qb) {
            #pragma unroll
            for (int qi = 0; qi < 8; ++qi) {
                const int q = wk * 32 + qb * 8 + qi;
                uint4 s0 = __ldcg(&g_Rf[dir][m2][q][0][lane]);
                uint4 s1 = __ldcg(&g_Rf[dir][m2][q][1][lane]);
                uint4 bb = *(const uint4*)&Bf2[((n2 * 64 + q) * 32 + lane) * 4];
                mmabf(C0, (const uint32_t*)&s0, bb.x, bb.y);
                mmabf(C1, (const uint32_t*)&s1, bb.x, bb.y);
                mmabf(C2, (const uint32_t*)&s0, bb.z, bb.w);
            }
        }
        __syncthreads();
        if (wk == 1) {
            #pragma unroll
            for (int i = 0; i < 4; ++i) {
                int r  = m2 * 16 + gid + (i >> 1) * 8;
                int cc = n2 * 8 + 2 * tig + (i & 1);
                red[r * 16 + cc] = C0[i] + C1[i] + C2[i];
            }
        }
        __syncthreads();
        if (wk == 0) {
            const float* __restrict__ xh = &g_Xh[dir][t][0][0];
            float hn[4];
            #pragma unroll
            for (int i = 0; i < 4; ++i) {
                int b  = m2 * 16 + gid + (i >> 1) * 8;
                int cc = n2 * 8 + 2 * tig + (i & 1);
                int j2 = c * 16 + cc;
                float sum = C0[i] + C1[i] + C2[i] + red[b * 16 + cc];
                float htil = tanhf(sum + xh[b * HH + j2]);
                float z    = __ldcg(&g_Z[dir][b][j2]);
                float hold = __ldcg(&g_hm[pcur][dir][b][j2]);
                float hnew = z * htil + (1.f - z) * hold;
                asm volatile("st.global.cg.f32 [%0], %1;"
                             :: "l"(&g_hm[pnxt][dir][b][j2]), "f"(hnew) : "memory");
                out[(size_t)(b * TT + t) * (2 * HH) + dir * HH + j2] = hnew;
                hn[i] = hnew;
            }
            int off = n2 * 8;
            uint2 u0 = make_uint2(pk(hn[0], hn[1]), pk(hn[2], hn[3]));
            uint2 u1 = make_uint2(pk(hn[0] - bhi(hn[0]), hn[1] - bhi(hn[1])),
                                  pk(hn[2] - bhi(hn[2]), hn[3] - bhi(hn[3])));
            asm volatile("st.global.cg.v2.u32 [%0], {%1,%2};"
                         :: "l"((char*)&g_hf[pnxt][dir][m2][c][0][lane] + off),
                            "r"(u0.x), "r"(u0.y) : "memory");
            asm volatile("st.global.cg.v2.u32 [%0], {%1,%2};"
                         :: "l"((char*)&g_hf[pnxt][dir][m2][c][1][lane] + off),
                            "r"(u1.x), "r"(u1.y) : "memory");
        }
        __syncthreads();
        if (tid == 0) publish_flag(&g_hflag[dir][c][0], 2u + step);
    }

    // ---- end of run: rendezvous (nobody still polls), reset flags to 0 ----
    dir_barrier(dir);
    if (tid == 0) {
        stcg_u32(&g_hflag [dir][c][0], 0u);
        stcg_u32(&g_rzflag[dir][c][0], 0u);
    }
    dir_barrier(dir);
}

// ---------------------------------------------------------------------------
extern "C" void kernel_launch(void* const* d_in, const int* in_sizes, int n_in,
                              void* d_out, int out_size) {
    (void)in_sizes; (void)n_in; (void)out_size;
    const float* x     = (const float*)d_in[0];
    const float* hf0   = (const float*)d_in[1];
    const float* hb0   = (const float*)d_in[2];
    const float* Whr_f = (const float*)d_in[3];
    const float* Wxr_f = (const float*)d_in[4];
    const float* br_f  = (const float*)d_in[5];
    const float* Whz_f = (const float*)d_in[6];
    const float* Wxz_f = (const float*)d_in[7];
    const float* bz_f  = (const float*)d_in[8];
    const float* Whh_f = (const float*)d_in[9];
    const float* Wxh_f = (const float*)d_in[10];
    const float* bh_f  = (const float*)d_in[11];
    const float* Whr_b = (const float*)d_in[12];
    const float* Wxr_b = (const float*)d_in[13];
    const float* br_b  = (const float*)d_in[14];
    const float* Whz_b = (const float*)d_in[15];
    const float* Wxz_b = (const float*)d_in[16];
    const float* bz_b  = (const float*)d_in[17];
    const float* Whh_b = (const float*)d_in[18];
    const float* Wxh_b = (const float*)d_in[19];
    const float* bh_b  = (const float*)d_in[20];
    float* out = (float*)d_out;

    static int smem_set = 0;
    if (!smem_set) {
        cudaFuncSetAttribute(gru_rec_kernel,
                             cudaFuncAttributeMaxDynamicSharedMemorySize,
                             SM_BYTES);
        smem_set = 1;
    }

    wprep_kernel<<<dim3(512, 3, 2), 256>>>(Wxr_f, Wxz_f, Wxh_f, Wxr_b, Wxz_b, Wxh_b);
    inproj_mma_kernel<<<dim3(256, 32, 2), 256>>>(x, br_f, bz_f, bh_f, br_b, bz_b, bh_b);
    gru_rec_kernel<<<2 * NCTA_DIR, 512, SM_BYTES>>>(hf0, hb0,
        Whr_f, Whz_f, Whh_f, Whr_b, Whz_b, Whh_b, out);
}